// round 12
// baseline (speedup 1.0000x reference)
#include <cuda_runtime.h>
#include <cuda_bf16.h>
#include <math.h>
#include <stdint.h>

#define BB 512
#define SS 64
#define TT 32
#define VV 128
#define EE 256
#define HH 512
#define DENC 1024
#define G4H 2048
#define EOS_IDX 2
#define PCOL (HH + DENC)  /* 1536 */

// ---------------- scratch (device globals; no allocations) ----------------
__device__ __nv_bfloat16 g_encproj_bf[(size_t)BB * SS * HH];  // 32 MB (score path)
__device__ __nv_bfloat16 g_enc_bf[(size_t)BB * SS * DENC];    // 64 MB (score-GEMM A)
__device__ __nv_bfloat16 g_Wenc_bf[HH * DENC];                // 1 MB  (score-GEMM B)
__device__ float g_pred[(size_t)BB * TT * PCOL];       // [h1n | context] (tf32-rounded)
__device__ float g_Wc0[G4H * (DENC + HH)];             // rounded [W_ih0[:,E:] | W_hh0]
__device__ float g_Wc1[G4H * (HH + HH)];               // rounded [W_ih1 | W_hh1]
__device__ float g_Wdec_r[HH * HH];                    // rounded W_dec
__device__ float g_Wout_r[VV * PCOL];                  // rounded compact W_out[:, :PCOL]
__device__ float g_token_gates[VV * G4H];              // per-token W_ih0[:, :E] @ emb
__device__ float g_token_preds[VV * VV];               // per-token W_out emb part + b_out
__device__ int   g_tokens[BB * TT];                    // input token per (b,t)
__device__ float g_xbuf[BB * (DENC + HH)];             // [context | h0] (tf32-rounded)
__device__ float g_x1buf[BB * (HH + HH)];              // [h0n | h1] (tf32-rounded)
__device__ float g_gates[BB * G4H];
__device__ float g_c0buf[BB * HH];
__device__ float g_c1buf[BB * HH];
__device__ float g_decproj[BB * HH];

__device__ __forceinline__ float sigmoid_fast(float x) {
    return __fdividef(1.0f, 1.0f + __expf(-x));
}
__device__ __forceinline__ float tanh_hw(float x) {
    float y;
    asm("tanh.approx.f32 %0, %1;" : "=f"(y) : "f"(x));
    return y;
}

__device__ __forceinline__ uint32_t f2tf32(float x) {
    uint32_t r;
    asm("cvt.rna.tf32.f32 %0, %1;" : "=r"(r) : "f"(x));
    return r;
}
__device__ __forceinline__ float tf32r(float x) { return __uint_as_float(f2tf32(x)); }

__device__ __forceinline__ uint32_t smem_u32(const void* p) {
    return (uint32_t)__cvta_generic_to_shared(p);
}
__device__ __forceinline__ void cp_async16(void* smem, const void* gmem) {
    asm volatile("cp.async.cg.shared.global [%0], [%1], 16;"
                 :: "r"(smem_u32(smem)), "l"(gmem));
}
__device__ __forceinline__ void cp_commit() {
    asm volatile("cp.async.commit_group;");
}
template <int N>
__device__ __forceinline__ void cp_wait() {
    asm volatile("cp.async.wait_group %0;" :: "n"(N));
}

__device__ __forceinline__ void mma_tf32(float* c, const uint32_t* a, const uint32_t* b) {
    asm volatile(
        "mma.sync.aligned.m16n8k8.row.col.f32.tf32.tf32.f32 "
        "{%0,%1,%2,%3},{%4,%5,%6,%7},{%8,%9},{%0,%1,%2,%3};"
        : "+f"(c[0]), "+f"(c[1]), "+f"(c[2]), "+f"(c[3])
        : "r"(a[0]), "r"(a[1]), "r"(a[2]), "r"(a[3]), "r"(b[0]), "r"(b[1]));
}
__device__ __forceinline__ void mma_bf16(float* c, const uint32_t* a, const uint32_t* b) {
    asm volatile(
        "mma.sync.aligned.m16n8k16.row.col.f32.bf16.bf16.f32 "
        "{%0,%1,%2,%3},{%4,%5,%6,%7},{%8,%9},{%0,%1,%2,%3};"
        : "+f"(c[0]), "+f"(c[1]), "+f"(c[2]), "+f"(c[3])
        : "r"(a[0]), "r"(a[1]), "r"(a[2]), "r"(a[3]), "r"(b[0]), "r"(b[1]));
}

// ---------------- TF32 tensor-core NT GEMM, multi-stage cp.async, 1 sync/tile --------
template <int BM, int BN, int BK, int WM, int WN, int STAGES, bool APRE, bool BPRE>
__global__ void __launch_bounds__((BM / WM) * (BN / WN) * 32,
                                  512 / ((BM / WM) * (BN / WN) * 32))
mma_nt_kernel(int M, int N, int K,
              const float* __restrict__ A, int lda,
              const float* __restrict__ B, int ldb,
              void* __restrict__ Cv, int ldc,
              const float* __restrict__ Cin, int ldcin,
              const float* __restrict__ bias0,
              const float* __restrict__ bias1,
              const int* __restrict__ rowtok, int rts,
              int accumulate, int out_bf16) {
    constexpr int WARPS_M = BM / WM, WARPS_N = BN / WN;
    constexpr int NW = WARPS_M * WARPS_N, THREADS = NW * 32;
    constexpr int MI = WM / 16, NI = WN / 8, KI = BK / 8;
    constexpr int LDS_ = BK + 4;
    constexpr int A_CP = BM * (BK / 4) / THREADS;
    constexpr int B_CP = BN * (BK / 4) / THREADS;

    __shared__ __align__(16) float As[STAGES][BM][LDS_];
    __shared__ __align__(16) float Bs[STAGES][BN][LDS_];

    const int tid = threadIdx.x;
    const int wid = tid >> 5, lane = tid & 31;
    const int wm = (wid / WARPS_N) * WM, wn = (wid % WARPS_N) * WN;
    const int g = lane >> 2, tg = lane & 3;
    const int bm = blockIdx.y * BM, bn = blockIdx.x * BN;

    float acc[MI][NI][4];
#pragma unroll
    for (int i = 0; i < MI; i++)
#pragma unroll
        for (int j = 0; j < NI; j++)
#pragma unroll
            for (int q = 0; q < 4; q++) acc[i][j][q] = 0.0f;

    auto issue_tile = [&](int tile, int slot) {
        const int k0 = tile * BK;
#pragma unroll
        for (int i = 0; i < A_CP; i++) {
            int idx = tid + i * THREADS;
            int m = idx / (BK / 4), kq = (idx % (BK / 4)) * 4;
            cp_async16(&As[slot][m][kq], A + (size_t)(bm + m) * lda + k0 + kq);
        }
#pragma unroll
        for (int i = 0; i < B_CP; i++) {
            int idx = tid + i * THREADS;
            int n = idx / (BK / 4), kq = (idx % (BK / 4)) * 4;
            cp_async16(&Bs[slot][n][kq], B + (size_t)(bn + n) * ldb + k0 + kq);
        }
    };

    const int ntiles = K / BK;
#pragma unroll
    for (int s = 0; s < STAGES - 1; s++) {
        issue_tile(s, s);
        cp_commit();
    }

    for (int t = 0; t < ntiles; t++) {
        cp_wait<STAGES - 2>();
        __syncthreads();
        const int slot = t % STAGES;

#pragma unroll
        for (int ki = 0; ki < KI; ki++) {
            const int k_lo = ki * 8 + tg, k_hi = k_lo + 4;
            uint32_t af[MI][4];
            uint32_t bfv[NI][2];
#pragma unroll
            for (int mi = 0; mi < MI; mi++) {
                const int mr = wm + mi * 16 + g;
                if (APRE) {
                    af[mi][0] = __float_as_uint(As[slot][mr][k_lo]);
                    af[mi][1] = __float_as_uint(As[slot][mr + 8][k_lo]);
                    af[mi][2] = __float_as_uint(As[slot][mr][k_hi]);
                    af[mi][3] = __float_as_uint(As[slot][mr + 8][k_hi]);
                } else {
                    af[mi][0] = f2tf32(As[slot][mr][k_lo]);
                    af[mi][1] = f2tf32(As[slot][mr + 8][k_lo]);
                    af[mi][2] = f2tf32(As[slot][mr][k_hi]);
                    af[mi][3] = f2tf32(As[slot][mr + 8][k_hi]);
                }
            }
#pragma unroll
            for (int ni = 0; ni < NI; ni++) {
                const int nr = wn + ni * 8 + g;
                if (BPRE) {
                    bfv[ni][0] = __float_as_uint(Bs[slot][nr][k_lo]);
                    bfv[ni][1] = __float_as_uint(Bs[slot][nr][k_hi]);
                } else {
                    bfv[ni][0] = f2tf32(Bs[slot][nr][k_lo]);
                    bfv[ni][1] = f2tf32(Bs[slot][nr][k_hi]);
                }
            }
#pragma unroll
            for (int mi = 0; mi < MI; mi++)
#pragma unroll
                for (int ni = 0; ni < NI; ni++) mma_tf32(acc[mi][ni], af[mi], bfv[ni]);
        }

        if (t + STAGES - 1 < ntiles) issue_tile(t + STAGES - 1, (t + STAGES - 1) % STAGES);
        cp_commit();
    }

    // epilogue
#pragma unroll
    for (int mi = 0; mi < MI; mi++) {
#pragma unroll
        for (int ni = 0; ni < NI; ni++) {
            const int col = bn + wn + ni * 8 + tg * 2;
#pragma unroll
            for (int half = 0; half < 2; half++) {
                const int row = bm + wm + mi * 16 + g + half * 8;
                float v0 = acc[mi][ni][half * 2 + 0];
                float v1 = acc[mi][ni][half * 2 + 1];
                if (out_bf16) {
                    __nv_bfloat162* cp =
                        (__nv_bfloat162*)((__nv_bfloat16*)Cv + (size_t)row * ldc + col);
                    *cp = __float22bfloat162_rn(make_float2(v0, v1));
                    continue;
                }
                float* C = (float*)Cv;
                if (bias0) { v0 += bias0[col]; v1 += bias0[col + 1]; }
                if (bias1) { v0 += bias1[col]; v1 += bias1[col + 1]; }
                if (Cin) {
                    const int crow = rowtok ? rowtok[row * rts] : row;
                    float2 ci = *(const float2*)(Cin + (size_t)crow * ldcin + col);
                    v0 += ci.x; v1 += ci.y;
                }
                float2* cp = (float2*)(C + (size_t)row * ldc + col);
                if (accumulate) {
                    float2 c = *cp;
                    v0 += c.x; v1 += c.y;
                }
                *cp = make_float2(v0, v1);
            }
        }
    }
}

template <int BM, int BN, int BK, int WM, int WN, int STAGES, bool APRE, bool BPRE>
static void mgemm(int M, int N, int K,
                  const float* A, int lda, const float* B, int ldb,
                  void* C, int ldc,
                  const float* Cin = nullptr, int ldcin = 0,
                  const float* bias0 = nullptr, const float* bias1 = nullptr,
                  const int* rowtok = nullptr, int rts = 1,
                  bool accumulate = false, bool out_bf16 = false) {
    dim3 grid(N / BN, M / BM);
    mma_nt_kernel<BM, BN, BK, WM, WN, STAGES, APRE, BPRE>
        <<<grid, (BM / WM) * (BN / WN) * 32>>>(
            M, N, K, A, lda, B, ldb, C, ldc, Cin, ldcin, bias0, bias1, rowtok, rts,
            accumulate ? 1 : 0, out_bf16 ? 1 : 0);
}

// ---------------- BF16 tensor-core NT GEMM (m16n8k16), bf16 in/out ----------------
// C[M,N] = A(MxK) * B(NxK)^T, all bf16, fp32 accum. Score path only.
template <int BM, int BN, int BK, int WM, int WN, int STAGES>
__global__ void __launch_bounds__((BM / WM) * (BN / WN) * 32, 1)
mma_nt_bf16_kernel(int M, int N, int K,
                   const __nv_bfloat16* __restrict__ A, int lda,
                   const __nv_bfloat16* __restrict__ B, int ldb,
                   __nv_bfloat16* __restrict__ C, int ldc) {
    constexpr int WARPS_M = BM / WM, WARPS_N = BN / WN;
    constexpr int NW = WARPS_M * WARPS_N, THREADS = NW * 32;
    constexpr int MI = WM / 16, NI = WN / 8, KI = BK / 16;
    constexpr int LDS_ = BK + 8;  // bf16 units; row = 80B -> conflict-free frag reads
    constexpr int A_CP = BM * (BK / 8) / THREADS;
    constexpr int B_CP = BN * (BK / 8) / THREADS;

    __shared__ __align__(16) __nv_bfloat16 As[STAGES][BM][LDS_];
    __shared__ __align__(16) __nv_bfloat16 Bs[STAGES][BN][LDS_];

    const int tid = threadIdx.x;
    const int wid = tid >> 5, lane = tid & 31;
    const int wm = (wid / WARPS_N) * WM, wn = (wid % WARPS_N) * WN;
    const int g = lane >> 2, tg = lane & 3;
    const int bm = blockIdx.y * BM, bn = blockIdx.x * BN;

    float acc[MI][NI][4];
#pragma unroll
    for (int i = 0; i < MI; i++)
#pragma unroll
        for (int j = 0; j < NI; j++)
#pragma unroll
            for (int q = 0; q < 4; q++) acc[i][j][q] = 0.0f;

    auto issue_tile = [&](int tile, int slot) {
        const int k0 = tile * BK;
#pragma unroll
        for (int i = 0; i < A_CP; i++) {
            int idx = tid + i * THREADS;
            int m = idx / (BK / 8), kq = (idx % (BK / 8)) * 8;
            cp_async16(&As[slot][m][kq], A + (size_t)(bm + m) * lda + k0 + kq);
        }
#pragma unroll
        for (int i = 0; i < B_CP; i++) {
            int idx = tid + i * THREADS;
            int n = idx / (BK / 8), kq = (idx % (BK / 8)) * 8;
            cp_async16(&Bs[slot][n][kq], B + (size_t)(bn + n) * ldb + k0 + kq);
        }
    };

    const int ntiles = K / BK;
#pragma unroll
    for (int s = 0; s < STAGES - 1; s++) {
        issue_tile(s, s);
        cp_commit();
    }

    for (int t = 0; t < ntiles; t++) {
        cp_wait<STAGES - 2>();
        __syncthreads();
        const int slot = t % STAGES;

#pragma unroll
        for (int ki = 0; ki < KI; ki++) {
            const int kb = ki * 16 + tg * 2;  // bf16 index, 4B-aligned
            uint32_t af[MI][4];
            uint32_t bfv[NI][2];
#pragma unroll
            for (int mi = 0; mi < MI; mi++) {
                const int mr = wm + mi * 16 + g;
                af[mi][0] = *(const uint32_t*)&As[slot][mr][kb];
                af[mi][1] = *(const uint32_t*)&As[slot][mr + 8][kb];
                af[mi][2] = *(const uint32_t*)&As[slot][mr][kb + 8];
                af[mi][3] = *(const uint32_t*)&As[slot][mr + 8][kb + 8];
            }
#pragma unroll
            for (int ni = 0; ni < NI; ni++) {
                const int nr = wn + ni * 8 + g;
                bfv[ni][0] = *(const uint32_t*)&Bs[slot][nr][kb];
                bfv[ni][1] = *(const uint32_t*)&Bs[slot][nr][kb + 8];
            }
#pragma unroll
            for (int mi = 0; mi < MI; mi++)
#pragma unroll
                for (int ni = 0; ni < NI; ni++) mma_bf16(acc[mi][ni], af[mi], bfv[ni]);
        }

        if (t + STAGES - 1 < ntiles) issue_tile(t + STAGES - 1, (t + STAGES - 1) % STAGES);
        cp_commit();
    }

#pragma unroll
    for (int mi = 0; mi < MI; mi++) {
#pragma unroll
        for (int ni = 0; ni < NI; ni++) {
            const int col = bn + wn + ni * 8 + tg * 2;
#pragma unroll
            for (int half = 0; half < 2; half++) {
                const int row = bm + wm + mi * 16 + g + half * 8;
                __nv_bfloat162* cp =
                    (__nv_bfloat162*)(C + (size_t)row * ldc + col);
                *cp = __float22bfloat162_rn(
                    make_float2(acc[mi][ni][half * 2], acc[mi][ni][half * 2 + 1]));
            }
        }
    }
}

// ---------------- precompute kernels ----------------
__global__ void tokens_kernel(const int* __restrict__ targets, int* __restrict__ toks) {
    int idx = blockIdx.x * blockDim.x + threadIdx.x;  // B*T
    int t = idx & (TT - 1);
    int b = idx >> 5;
    toks[idx] = (t == 0) ? EOS_IDX : targets[b * TT + t - 1];
}

__global__ void build_wcomb_kernel(const float* __restrict__ W_ih0,
                                   const float* __restrict__ W_hh0,
                                   const float* __restrict__ W_ih1,
                                   const float* __restrict__ W_hh1,
                                   float* __restrict__ Wc0,
                                   float* __restrict__ Wc1) {
    int idx = blockIdx.x * blockDim.x + threadIdx.x;
    const int N0 = G4H * (DENC + HH);
    const int N1 = G4H * (HH + HH);
    if (idx < N0) {
        int n = idx / (DENC + HH);
        int k = idx % (DENC + HH);
        float v = (k < DENC) ? W_ih0[(size_t)n * (EE + DENC) + EE + k]
                             : W_hh0[(size_t)n * HH + (k - DENC)];
        Wc0[idx] = tf32r(v);
    } else if (idx < N0 + N1) {
        int r = idx - N0;
        int n = r / (HH + HH);
        int k = r % (HH + HH);
        float v = (k < HH) ? W_ih1[(size_t)n * HH + k]
                           : W_hh1[(size_t)n * HH + (k - HH)];
        Wc1[r] = tf32r(v);
    }
}

// rounded Wdec/Wout (tf32) + bf16 Wenc
__global__ void round_weights_kernel(const float* __restrict__ W_dec,
                                     const float* __restrict__ W_enc,
                                     const float* __restrict__ W_out,
                                     float* __restrict__ Wdec_r,
                                     __nv_bfloat16* __restrict__ Wenc_bf,
                                     float* __restrict__ Wout_r) {
    int idx = blockIdx.x * blockDim.x + threadIdx.x;
    const int N0 = HH * HH;
    const int N1 = HH * DENC;
    const int N2 = VV * PCOL;
    if (idx < N0) {
        Wdec_r[idx] = tf32r(W_dec[idx]);
    } else if (idx < N0 + N1) {
        int r = idx - N0;
        Wenc_bf[r] = __float2bfloat16_rn(W_enc[r]);
    } else if (idx < N0 + N1 + N2) {
        int r = idx - N0 - N1;
        int row = r / PCOL, col = r % PCOL;
        Wout_r[r] = tf32r(W_out[(size_t)row * (HH + DENC + EE) + col]);
    }
}

// fp32 -> bf16 bulk convert (4 elems/thread)
__global__ void cvt_bf16_kernel(const float* __restrict__ in,
                                __nv_bfloat16* __restrict__ out, int n4) {
    int i = blockIdx.x * blockDim.x + threadIdx.x;
    if (i < n4) {
        float4 v = ((const float4*)in)[i];
        ((__nv_bfloat162*)out)[2 * i] = __float22bfloat162_rn(make_float2(v.x, v.y));
        ((__nv_bfloat162*)out)[2 * i + 1] = __float22bfloat162_rn(make_float2(v.z, v.w));
    }
}

__global__ void init_state_kernel(const float* __restrict__ h0,
                                  const float* __restrict__ c0,
                                  float* __restrict__ xbuf,
                                  float* __restrict__ x1buf,
                                  float* __restrict__ cb0,
                                  float* __restrict__ cb1) {
    int idx = blockIdx.x * blockDim.x + threadIdx.x;  // B*H
    int b = idx >> 9;
    int h = idx & (HH - 1);
    xbuf[(size_t)b * (DENC + HH) + DENC + h] = tf32r(h0[idx]);
    x1buf[(size_t)b * (HH + HH) + HH + h] = tf32r(h0[(size_t)BB * HH + idx]);
    cb0[idx] = c0[idx];
    cb1[idx] = c0[(size_t)BB * HH + idx];
}

// ---------------- attention (fused score/tanh + masked softmax + context) ----------------
__global__ void __launch_bounds__(256) attention_kernel(
    const __nv_bfloat16* __restrict__ enc_proj,   // (B,S,H) bf16
    const float* __restrict__ enc,        // (B,S,DENC) fp32
    const float* __restrict__ decp,       // (B,H)
    const float* __restrict__ vvec,       // (H)
    const int* __restrict__ mask,         // (B,S)
    float* __restrict__ ctx_dst1, int ld1,
    float* __restrict__ ctx_dst2, int ld2) {
    const int b = blockIdx.x;
    __shared__ float s_dp[HH];
    __shared__ float s_v[HH];
    __shared__ float s_w[SS];
    __shared__ float s_red[2];
    const int tid = threadIdx.x;
    const int warp = tid >> 5, lane = tid & 31;

    for (int i = tid; i < HH; i += 256) {
        s_dp[i] = decp[(size_t)b * HH + i];
        s_v[i] = vvec[i];
    }
    __syncthreads();

    for (int s = warp; s < SS; s += 8) {
        const __nv_bfloat162* ep =
            (const __nv_bfloat162*)(enc_proj + ((size_t)b * SS + s) * HH);
        float acc = 0.0f;
#pragma unroll 4
        for (int h2 = lane; h2 < HH / 2; h2 += 32) {
            float2 e = __bfloat1622float2(ep[h2]);
            acc += s_v[2 * h2] * tanh_hw(s_dp[2 * h2] + e.x);
            acc += s_v[2 * h2 + 1] * tanh_hw(s_dp[2 * h2 + 1] + e.y);
        }
#pragma unroll
        for (int o = 16; o; o >>= 1) acc += __shfl_xor_sync(0xffffffffu, acc, o);
        if (lane == 0) s_w[s] = mask[b * SS + s] ? acc : -1e30f;
    }
    __syncthreads();

    if (warp == 0) {
        float m = fmaxf(s_w[lane], s_w[lane + 32]);
#pragma unroll
        for (int o = 16; o; o >>= 1) m = fmaxf(m, __shfl_xor_sync(0xffffffffu, m, o));
        float sum = __expf(s_w[lane] - m) + __expf(s_w[lane + 32] - m);
#pragma unroll
        for (int o = 16; o; o >>= 1) sum += __shfl_xor_sync(0xffffffffu, sum, o);
        if (lane == 0) { s_red[0] = m; s_red[1] = sum; }
    }
    __syncthreads();
    const float m = s_red[0], inv = 1.0f / s_red[1];
    if (tid < SS) s_w[tid] = __expf(s_w[tid] - m) * inv;
    __syncthreads();

    const float4* eb4 = (const float4*)(enc + (size_t)b * SS * DENC);
    float4 acc4 = make_float4(0.f, 0.f, 0.f, 0.f);
#pragma unroll 8
    for (int s = 0; s < SS; s++) {
        const float w = s_w[s];
        float4 e = eb4[(size_t)s * (DENC / 4) + tid];
        acc4.x += w * e.x; acc4.y += w * e.y;
        acc4.z += w * e.z; acc4.w += w * e.w;
    }
    acc4.x = tf32r(acc4.x); acc4.y = tf32r(acc4.y);
    acc4.z = tf32r(acc4.z); acc4.w = tf32r(acc4.w);
    *(float4*)(ctx_dst1 + (size_t)b * ld1 + 4 * tid) = acc4;
    *(float4*)(ctx_dst2 + (size_t)b * ld2 + 4 * tid) = acc4;
}

// ---------------- LSTM pointwise cell (vectorized, plain gate layout) ----------------
__global__ void lstm_cell_kernel(const float* __restrict__ gates,  // (B,4H)
                                 float* __restrict__ c,            // (B,H) in/out
                                 float* __restrict__ hA, int ldA,
                                 float* __restrict__ hB, int ldB) {
    int idx = blockIdx.x * blockDim.x + threadIdx.x;  // B*H/4
    int b = idx / (HH / 4);
    int q = idx % (HH / 4);
    const float* gp = gates + (size_t)b * G4H + 4 * q;
    float4 gi = *(const float4*)(gp);
    float4 gf = *(const float4*)(gp + HH);
    float4 gg = *(const float4*)(gp + 2 * HH);
    float4 go = *(const float4*)(gp + 3 * HH);
    float4 cc = *(float4*)(c + (size_t)b * HH + 4 * q);
    float4 cn, hn;
    cn.x = sigmoid_fast(gf.x) * cc.x + sigmoid_fast(gi.x) * tanhf(gg.x);
    cn.y = sigmoid_fast(gf.y) * cc.y + sigmoid_fast(gi.y) * tanhf(gg.y);
    cn.z = sigmoid_fast(gf.z) * cc.z + sigmoid_fast(gi.z) * tanhf(gg.z);
    cn.w = sigmoid_fast(gf.w) * cc.w + sigmoid_fast(gi.w) * tanhf(gg.w);
    hn.x = tf32r(sigmoid_fast(go.x) * tanhf(cn.x));
    hn.y = tf32r(sigmoid_fast(go.y) * tanhf(cn.y));
    hn.z = tf32r(sigmoid_fast(go.z) * tanhf(cn.z));
    hn.w = tf32r(sigmoid_fast(go.w) * tanhf(cn.w));
    *(float4*)(c + (size_t)b * HH + 4 * q) = cn;
    *(float4*)(hA + (size_t)b * ldA + 4 * q) = hn;
    *(float4*)(hB + (size_t)b * ldB + 4 * q) = hn;
}

// ---------------- host ----------------
extern "C" void kernel_launch(void* const* d_in, const int* in_sizes, int n_in,
                              void* d_out, int out_size) {
    const float* encoder_out = (const float*)d_in[0];
    const float* h0   = (const float*)d_in[1];
    const float* c0   = (const float*)d_in[2];
    const int*   targets = (const int*)d_in[3];
    const int*   mask    = (const int*)d_in[4];
    const float* emb   = (const float*)d_in[5];
    const float* W_enc = (const float*)d_in[6];
    const float* W_dec = (const float*)d_in[7];
    const float* vvec  = (const float*)d_in[8];
    const float* W_ih0 = (const float*)d_in[9];
    const float* W_hh0 = (const float*)d_in[10];
    const float* b_ih0 = (const float*)d_in[11];
    const float* b_hh0 = (const float*)d_in[12];
    const float* W_ih1 = (const float*)d_in[13];
    const float* W_hh1 = (const float*)d_in[14];
    const float* b_ih1 = (const float*)d_in[15];
    const float* b_hh1 = (const float*)d_in[16];
    const float* W_out = (const float*)d_in[17];
    const float* b_out = (const float*)d_in[18];
    float* out = (float*)d_out;  // (B,T,V)

    __nv_bfloat16 *p_encproj_bf, *p_enc_bf, *p_Wenc_bf;
    float *p_pred, *p_Wc0, *p_Wc1, *p_Wdec, *p_Wout, *p_tokg, *p_tokp;
    float *p_xbuf, *p_x1buf, *p_gates, *p_c0, *p_c1, *p_decproj;
    int* p_tokens;
    cudaGetSymbolAddress((void**)&p_encproj_bf, g_encproj_bf);
    cudaGetSymbolAddress((void**)&p_enc_bf, g_enc_bf);
    cudaGetSymbolAddress((void**)&p_Wenc_bf, g_Wenc_bf);
    cudaGetSymbolAddress((void**)&p_pred, g_pred);
    cudaGetSymbolAddress((void**)&p_Wc0, g_Wc0);
    cudaGetSymbolAddress((void**)&p_Wc1, g_Wc1);
    cudaGetSymbolAddress((void**)&p_Wdec, g_Wdec_r);
    cudaGetSymbolAddress((void**)&p_Wout, g_Wout_r);
    cudaGetSymbolAddress((void**)&p_tokg, g_token_gates);
    cudaGetSymbolAddress((void**)&p_tokp, g_token_preds);
    cudaGetSymbolAddress((void**)&p_tokens, g_tokens);
    cudaGetSymbolAddress((void**)&p_xbuf, g_xbuf);
    cudaGetSymbolAddress((void**)&p_x1buf, g_x1buf);
    cudaGetSymbolAddress((void**)&p_gates, g_gates);
    cudaGetSymbolAddress((void**)&p_c0, g_c0buf);
    cudaGetSymbolAddress((void**)&p_c1, g_c1buf);
    cudaGetSymbolAddress((void**)&p_decproj, g_decproj);

    // ---- precompute ----
    tokens_kernel<<<(BB * TT) / 256, 256>>>(targets, p_tokens);
    {
        int total = G4H * (DENC + HH) + G4H * (HH + HH);
        build_wcomb_kernel<<<(total + 255) / 256, 256>>>(W_ih0, W_hh0, W_ih1, W_hh1,
                                                         p_Wc0, p_Wc1);
    }
    {
        int total = HH * HH + HH * DENC + VV * PCOL;
        round_weights_kernel<<<(total + 255) / 256, 256>>>(W_dec, W_enc, W_out,
                                                           p_Wdec, p_Wenc_bf, p_Wout);
    }
    {
        int n4 = (BB * SS * DENC) / 4;
        cvt_bf16_kernel<<<(n4 + 255) / 256, 256>>>(encoder_out, p_enc_bf, n4);
    }
    init_state_kernel<<<(BB * HH) / 256, 256>>>(h0, c0, p_xbuf, p_x1buf, p_c0, p_c1);

    // token_gates (V,4H) = emb @ W_ih0[:, :E]^T   (raw operands)
    mgemm<64, 128, 16, 32, 64, 4, false, false>(VV, G4H, EE, emb, EE, W_ih0, EE + DENC,
                                                p_tokg, G4H);
    // token_preds (V,V) = emb @ W_out[:, H+DENC:]^T + b_out
    mgemm<64, 64, 16, 32, 32, 4, false, false>(VV, VV, EE, emb, EE,
                                               W_out + (HH + DENC), HH + DENC + EE,
                                               p_tokp, VV, nullptr, 0, b_out);
    // enc_proj -> bf16 (score path only): full-bf16 tensor-core GEMM
    {
        dim3 grid(HH / 128, (BB * SS) / 128);
        mma_nt_bf16_kernel<128, 128, 32, 64, 32, 3><<<grid, 256>>>(
            BB * SS, HH, DENC, p_enc_bf, DENC, p_Wenc_bf, DENC, p_encproj_bf, HH);
    }

    // ---- sequential decode ----
    for (int t = 0; t < TT; t++) {
        // dec_proj = h1 @ Wdec_r^T   (pre-rounded operands)
        mgemm<64, 64, 16, 32, 32, 4, true, true>(BB, HH, HH, p_x1buf + HH, HH + HH,
                                                 p_Wdec, HH, p_decproj, HH);

        // attention: context -> xbuf[:, :DENC] and pred[:, t, H:]
        attention_kernel<<<BB, 256>>>(p_encproj_bf, encoder_out, p_decproj, vvec, mask,
                                      p_xbuf, DENC + HH,
                                      p_pred + (size_t)t * PCOL + HH, TT * PCOL);

        // gates0 = [context|h0] @ Wc0^T + token_gates[tok(b,t)] + b_ih0 + b_hh0
        mgemm<64, 128, 16, 32, 64, 4, true, true>(BB, G4H, DENC + HH, p_xbuf, DENC + HH,
                                                  p_Wc0, DENC + HH, p_gates, G4H,
                                                  p_tokg, G4H, b_ih0, b_hh0,
                                                  p_tokens + t, TT);
        lstm_cell_kernel<<<(BB * HH / 4) / 256, 256>>>(p_gates, p_c0,
                                                       p_x1buf, HH + HH,
                                                       p_xbuf + DENC, DENC + HH);

        // gates1 = [h0n|h1] @ Wc1^T + b_ih1 + b_hh1
        mgemm<64, 128, 16, 32, 64, 4, true, true>(BB, G4H, HH + HH, p_x1buf, HH + HH,
                                                  p_Wc1, HH + HH, p_gates, G4H,
                                                  nullptr, 0, b_ih1, b_hh1);
        lstm_cell_kernel<<<(BB * HH / 4) / 256, 256>>>(p_gates, p_c1,
                                                       p_x1buf + HH, HH + HH,
                                                       p_pred + (size_t)t * PCOL, TT * PCOL);
    }

    // logits: out = [h1n|context] @ Wout_r^T + token_preds[tok(b,t)]  (BM64: 256 CTAs)
    mgemm<64, 128, 16, 32, 64, 4, true, true>(BB * TT, VV, PCOL, p_pred, PCOL,
                                              p_Wout, PCOL, out, VV,
                                              p_tokp, VV, nullptr, nullptr,
                                              p_tokens, 1);
}

// round 13
// speedup vs baseline: 1.1045x; 1.1045x over previous
#include <cuda_runtime.h>
#include <cuda_fp16.h>
#include <math.h>
#include <stdint.h>

#define BB 512
#define SS 64
#define TT 32
#define VV 128
#define EE 256
#define HH 512
#define DENC 1024
#define G4H 2048
#define EOS_IDX 2
#define PCOL (HH + DENC)  /* 1536 */

// ---------------- scratch (device globals; no allocations) ----------------
__device__ __half g_encproj_h[(size_t)BB * SS * HH];   // 32 MB (score path)
__device__ __half g_enc_h[(size_t)BB * SS * DENC];     // 64 MB (attention + enc_proj A)
__device__ __half g_Wenc_h[HH * DENC];                 // 1 MB
__device__ float g_pred[(size_t)BB * TT * PCOL];       // [h1n | context] (tf32-rounded)
__device__ float g_Wc0[G4H * (DENC + HH)];             // rounded [W_ih0[:,E:] | W_hh0]
__device__ float g_Wc1[G4H * (HH + HH)];               // rounded [W_ih1 | W_hh1]
__device__ float g_Wdec_r[HH * HH];                    // rounded W_dec
__device__ float g_Wout_r[VV * PCOL];                  // rounded compact W_out[:, :PCOL]
__device__ float g_token_gates[VV * G4H];              // per-token W_ih0[:, :E] @ emb
__device__ float g_token_preds[VV * VV];               // per-token W_out emb part + b_out
__device__ int   g_tokens[BB * TT];                    // input token per (b,t)
__device__ float g_xbuf[BB * (DENC + HH)];             // [context | h0] (tf32-rounded)
__device__ float g_x1buf[BB * (HH + HH)];              // [h0n | h1] (tf32-rounded)
__device__ float g_gates[BB * G4H];
__device__ float g_c0buf[BB * HH];
__device__ float g_c1buf[BB * HH];
__device__ float g_decproj[BB * HH];

__device__ __forceinline__ float sigmoid_fast(float x) {
    return __fdividef(1.0f, 1.0f + __expf(-x));
}
__device__ __forceinline__ float tanh_hw(float x) {
    float y;
    asm("tanh.approx.f32 %0, %1;" : "=f"(y) : "f"(x));
    return y;
}

__device__ __forceinline__ uint32_t f2tf32(float x) {
    uint32_t r;
    asm("cvt.rna.tf32.f32 %0, %1;" : "=r"(r) : "f"(x));
    return r;
}
__device__ __forceinline__ float tf32r(float x) { return __uint_as_float(f2tf32(x)); }

__device__ __forceinline__ uint32_t smem_u32(const void* p) {
    return (uint32_t)__cvta_generic_to_shared(p);
}
__device__ __forceinline__ void cp_async16(void* smem, const void* gmem) {
    asm volatile("cp.async.cg.shared.global [%0], [%1], 16;"
                 :: "r"(smem_u32(smem)), "l"(gmem));
}
__device__ __forceinline__ void cp_commit() {
    asm volatile("cp.async.commit_group;");
}
template <int N>
__device__ __forceinline__ void cp_wait() {
    asm volatile("cp.async.wait_group %0;" :: "n"(N));
}

__device__ __forceinline__ void mma_tf32(float* c, const uint32_t* a, const uint32_t* b) {
    asm volatile(
        "mma.sync.aligned.m16n8k8.row.col.f32.tf32.tf32.f32 "
        "{%0,%1,%2,%3},{%4,%5,%6,%7},{%8,%9},{%0,%1,%2,%3};"
        : "+f"(c[0]), "+f"(c[1]), "+f"(c[2]), "+f"(c[3])
        : "r"(a[0]), "r"(a[1]), "r"(a[2]), "r"(a[3]), "r"(b[0]), "r"(b[1]));
}
__device__ __forceinline__ void mma_f16(float* c, const uint32_t* a, const uint32_t* b) {
    asm volatile(
        "mma.sync.aligned.m16n8k16.row.col.f32.f16.f16.f32 "
        "{%0,%1,%2,%3},{%4,%5,%6,%7},{%8,%9},{%0,%1,%2,%3};"
        : "+f"(c[0]), "+f"(c[1]), "+f"(c[2]), "+f"(c[3])
        : "r"(a[0]), "r"(a[1]), "r"(a[2]), "r"(a[3]), "r"(b[0]), "r"(b[1]));
}

// ---------------- TF32 tensor-core NT GEMM, multi-stage cp.async, 1 sync/tile --------
template <int BM, int BN, int BK, int WM, int WN, int STAGES, bool APRE, bool BPRE>
__global__ void __launch_bounds__((BM / WM) * (BN / WN) * 32,
                                  512 / ((BM / WM) * (BN / WN) * 32))
mma_nt_kernel(int M, int N, int K,
              const float* __restrict__ A, int lda,
              const float* __restrict__ B, int ldb,
              void* __restrict__ Cv, int ldc,
              const float* __restrict__ Cin, int ldcin,
              const float* __restrict__ bias0,
              const float* __restrict__ bias1,
              const int* __restrict__ rowtok, int rts,
              int accumulate) {
    constexpr int WARPS_M = BM / WM, WARPS_N = BN / WN;
    constexpr int NW = WARPS_M * WARPS_N, THREADS = NW * 32;
    constexpr int MI = WM / 16, NI = WN / 8, KI = BK / 8;
    constexpr int LDS_ = BK + 4;
    constexpr int A_CP = BM * (BK / 4) / THREADS;
    constexpr int B_CP = BN * (BK / 4) / THREADS;

    __shared__ __align__(16) float As[STAGES][BM][LDS_];
    __shared__ __align__(16) float Bs[STAGES][BN][LDS_];

    const int tid = threadIdx.x;
    const int wid = tid >> 5, lane = tid & 31;
    const int wm = (wid / WARPS_N) * WM, wn = (wid % WARPS_N) * WN;
    const int g = lane >> 2, tg = lane & 3;
    const int bm = blockIdx.y * BM, bn = blockIdx.x * BN;

    float acc[MI][NI][4];
#pragma unroll
    for (int i = 0; i < MI; i++)
#pragma unroll
        for (int j = 0; j < NI; j++)
#pragma unroll
            for (int q = 0; q < 4; q++) acc[i][j][q] = 0.0f;

    auto issue_tile = [&](int tile, int slot) {
        const int k0 = tile * BK;
#pragma unroll
        for (int i = 0; i < A_CP; i++) {
            int idx = tid + i * THREADS;
            int m = idx / (BK / 4), kq = (idx % (BK / 4)) * 4;
            cp_async16(&As[slot][m][kq], A + (size_t)(bm + m) * lda + k0 + kq);
        }
#pragma unroll
        for (int i = 0; i < B_CP; i++) {
            int idx = tid + i * THREADS;
            int n = idx / (BK / 4), kq = (idx % (BK / 4)) * 4;
            cp_async16(&Bs[slot][n][kq], B + (size_t)(bn + n) * ldb + k0 + kq);
        }
    };

    const int ntiles = K / BK;
#pragma unroll
    for (int s = 0; s < STAGES - 1; s++) {
        issue_tile(s, s);
        cp_commit();
    }

    for (int t = 0; t < ntiles; t++) {
        cp_wait<STAGES - 2>();
        __syncthreads();
        const int slot = t % STAGES;

#pragma unroll
        for (int ki = 0; ki < KI; ki++) {
            const int k_lo = ki * 8 + tg, k_hi = k_lo + 4;
            uint32_t af[MI][4];
            uint32_t bfv[NI][2];
#pragma unroll
            for (int mi = 0; mi < MI; mi++) {
                const int mr = wm + mi * 16 + g;
                if (APRE) {
                    af[mi][0] = __float_as_uint(As[slot][mr][k_lo]);
                    af[mi][1] = __float_as_uint(As[slot][mr + 8][k_lo]);
                    af[mi][2] = __float_as_uint(As[slot][mr][k_hi]);
                    af[mi][3] = __float_as_uint(As[slot][mr + 8][k_hi]);
                } else {
                    af[mi][0] = f2tf32(As[slot][mr][k_lo]);
                    af[mi][1] = f2tf32(As[slot][mr + 8][k_lo]);
                    af[mi][2] = f2tf32(As[slot][mr][k_hi]);
                    af[mi][3] = f2tf32(As[slot][mr + 8][k_hi]);
                }
            }
#pragma unroll
            for (int ni = 0; ni < NI; ni++) {
                const int nr = wn + ni * 8 + g;
                if (BPRE) {
                    bfv[ni][0] = __float_as_uint(Bs[slot][nr][k_lo]);
                    bfv[ni][1] = __float_as_uint(Bs[slot][nr][k_hi]);
                } else {
                    bfv[ni][0] = f2tf32(Bs[slot][nr][k_lo]);
                    bfv[ni][1] = f2tf32(Bs[slot][nr][k_hi]);
                }
            }
#pragma unroll
            for (int mi = 0; mi < MI; mi++)
#pragma unroll
                for (int ni = 0; ni < NI; ni++) mma_tf32(acc[mi][ni], af[mi], bfv[ni]);
        }

        if (t + STAGES - 1 < ntiles) issue_tile(t + STAGES - 1, (t + STAGES - 1) % STAGES);
        cp_commit();
    }

    // epilogue
#pragma unroll
    for (int mi = 0; mi < MI; mi++) {
#pragma unroll
        for (int ni = 0; ni < NI; ni++) {
            const int col = bn + wn + ni * 8 + tg * 2;
#pragma unroll
            for (int half = 0; half < 2; half++) {
                const int row = bm + wm + mi * 16 + g + half * 8;
                float v0 = acc[mi][ni][half * 2 + 0];
                float v1 = acc[mi][ni][half * 2 + 1];
                float* C = (float*)Cv;
                if (bias0) { v0 += bias0[col]; v1 += bias0[col + 1]; }
                if (bias1) { v0 += bias1[col]; v1 += bias1[col + 1]; }
                if (Cin) {
                    const int crow = rowtok ? rowtok[row * rts] : row;
                    float2 ci = *(const float2*)(Cin + (size_t)crow * ldcin + col);
                    v0 += ci.x; v1 += ci.y;
                }
                float2* cp = (float2*)(C + (size_t)row * ldc + col);
                if (accumulate) {
                    float2 c = *cp;
                    v0 += c.x; v1 += c.y;
                }
                *cp = make_float2(v0, v1);
            }
        }
    }
}

template <int BM, int BN, int BK, int WM, int WN, int STAGES, bool APRE, bool BPRE>
static void mgemm(int M, int N, int K,
                  const float* A, int lda, const float* B, int ldb,
                  void* C, int ldc,
                  const float* Cin = nullptr, int ldcin = 0,
                  const float* bias0 = nullptr, const float* bias1 = nullptr,
                  const int* rowtok = nullptr, int rts = 1,
                  bool accumulate = false) {
    dim3 grid(N / BN, M / BM);
    mma_nt_kernel<BM, BN, BK, WM, WN, STAGES, APRE, BPRE>
        <<<grid, (BM / WM) * (BN / WN) * 32>>>(
            M, N, K, A, lda, B, ldb, C, ldc, Cin, ldcin, bias0, bias1, rowtok, rts,
            accumulate ? 1 : 0);
}

// ---------------- FP16 tensor-core NT GEMM (m16n8k16), fp16 in/out ----------------
// C[M,N] = A(MxK) * B(NxK)^T, fp16 operands, fp32 accum, fp16 out. Score path only.
template <int BM, int BN, int BK, int WM, int WN, int STAGES>
__global__ void __launch_bounds__((BM / WM) * (BN / WN) * 32, 1)
mma_nt_f16_kernel(int M, int N, int K,
                  const __half* __restrict__ A, int lda,
                  const __half* __restrict__ B, int ldb,
                  __half* __restrict__ C, int ldc) {
    constexpr int WARPS_M = BM / WM, WARPS_N = BN / WN;
    constexpr int NW = WARPS_M * WARPS_N, THREADS = NW * 32;
    constexpr int MI = WM / 16, NI = WN / 8, KI = BK / 16;
    constexpr int LDS_ = BK + 8;  // halves; 80B row -> conflict-free frag reads
    constexpr int A_CP = BM * (BK / 8) / THREADS;
    constexpr int B_CP = BN * (BK / 8) / THREADS;

    __shared__ __align__(16) __half As[STAGES][BM][LDS_];
    __shared__ __align__(16) __half Bs[STAGES][BN][LDS_];

    const int tid = threadIdx.x;
    const int wid = tid >> 5, lane = tid & 31;
    const int wm = (wid / WARPS_N) * WM, wn = (wid % WARPS_N) * WN;
    const int g = lane >> 2, tg = lane & 3;
    const int bm = blockIdx.y * BM, bn = blockIdx.x * BN;

    float acc[MI][NI][4];
#pragma unroll
    for (int i = 0; i < MI; i++)
#pragma unroll
        for (int j = 0; j < NI; j++)
#pragma unroll
            for (int q = 0; q < 4; q++) acc[i][j][q] = 0.0f;

    auto issue_tile = [&](int tile, int slot) {
        const int k0 = tile * BK;
#pragma unroll
        for (int i = 0; i < A_CP; i++) {
            int idx = tid + i * THREADS;
            int m = idx / (BK / 8), kq = (idx % (BK / 8)) * 8;
            cp_async16(&As[slot][m][kq], A + (size_t)(bm + m) * lda + k0 + kq);
        }
#pragma unroll
        for (int i = 0; i < B_CP; i++) {
            int idx = tid + i * THREADS;
            int n = idx / (BK / 8), kq = (idx % (BK / 8)) * 8;
            cp_async16(&Bs[slot][n][kq], B + (size_t)(bn + n) * ldb + k0 + kq);
        }
    };

    const int ntiles = K / BK;
#pragma unroll
    for (int s = 0; s < STAGES - 1; s++) {
        issue_tile(s, s);
        cp_commit();
    }

    for (int t = 0; t < ntiles; t++) {
        cp_wait<STAGES - 2>();
        __syncthreads();
        const int slot = t % STAGES;

#pragma unroll
        for (int ki = 0; ki < KI; ki++) {
            const int kb = ki * 16 + tg * 2;
            uint32_t af[MI][4];
            uint32_t bfv[NI][2];
#pragma unroll
            for (int mi = 0; mi < MI; mi++) {
                const int mr = wm + mi * 16 + g;
                af[mi][0] = *(const uint32_t*)&As[slot][mr][kb];
                af[mi][1] = *(const uint32_t*)&As[slot][mr + 8][kb];
                af[mi][2] = *(const uint32_t*)&As[slot][mr][kb + 8];
                af[mi][3] = *(const uint32_t*)&As[slot][mr + 8][kb + 8];
            }
#pragma unroll
            for (int ni = 0; ni < NI; ni++) {
                const int nr = wn + ni * 8 + g;
                bfv[ni][0] = *(const uint32_t*)&Bs[slot][nr][kb];
                bfv[ni][1] = *(const uint32_t*)&Bs[slot][nr][kb + 8];
            }
#pragma unroll
            for (int mi = 0; mi < MI; mi++)
#pragma unroll
                for (int ni = 0; ni < NI; ni++) mma_f16(acc[mi][ni], af[mi], bfv[ni]);
        }

        if (t + STAGES - 1 < ntiles) issue_tile(t + STAGES - 1, (t + STAGES - 1) % STAGES);
        cp_commit();
    }

#pragma unroll
    for (int mi = 0; mi < MI; mi++) {
#pragma unroll
        for (int ni = 0; ni < NI; ni++) {
            const int col = bn + wn + ni * 8 + tg * 2;
#pragma unroll
            for (int half = 0; half < 2; half++) {
                const int row = bm + wm + mi * 16 + g + half * 8;
                __half2* cp = (__half2*)(C + (size_t)row * ldc + col);
                *cp = __floats2half2_rn(acc[mi][ni][half * 2], acc[mi][ni][half * 2 + 1]);
            }
        }
    }
}

// ---------------- precompute kernels ----------------
__global__ void tokens_kernel(const int* __restrict__ targets, int* __restrict__ toks) {
    int idx = blockIdx.x * blockDim.x + threadIdx.x;  // B*T
    int t = idx & (TT - 1);
    int b = idx >> 5;
    toks[idx] = (t == 0) ? EOS_IDX : targets[b * TT + t - 1];
}

__global__ void build_wcomb_kernel(const float* __restrict__ W_ih0,
                                   const float* __restrict__ W_hh0,
                                   const float* __restrict__ W_ih1,
                                   const float* __restrict__ W_hh1,
                                   float* __restrict__ Wc0,
                                   float* __restrict__ Wc1) {
    int idx = blockIdx.x * blockDim.x + threadIdx.x;
    const int N0 = G4H * (DENC + HH);
    const int N1 = G4H * (HH + HH);
    if (idx < N0) {
        int n = idx / (DENC + HH);
        int k = idx % (DENC + HH);
        float v = (k < DENC) ? W_ih0[(size_t)n * (EE + DENC) + EE + k]
                             : W_hh0[(size_t)n * HH + (k - DENC)];
        Wc0[idx] = tf32r(v);
    } else if (idx < N0 + N1) {
        int r = idx - N0;
        int n = r / (HH + HH);
        int k = r % (HH + HH);
        float v = (k < HH) ? W_ih1[(size_t)n * HH + k]
                           : W_hh1[(size_t)n * HH + (k - HH)];
        Wc1[r] = tf32r(v);
    }
}

// rounded Wdec/Wout (tf32) + fp16 Wenc
__global__ void round_weights_kernel(const float* __restrict__ W_dec,
                                     const float* __restrict__ W_enc,
                                     const float* __restrict__ W_out,
                                     float* __restrict__ Wdec_r,
                                     __half* __restrict__ Wenc_h,
                                     float* __restrict__ Wout_r) {
    int idx = blockIdx.x * blockDim.x + threadIdx.x;
    const int N0 = HH * HH;
    const int N1 = HH * DENC;
    const int N2 = VV * PCOL;
    if (idx < N0) {
        Wdec_r[idx] = tf32r(W_dec[idx]);
    } else if (idx < N0 + N1) {
        int r = idx - N0;
        Wenc_h[r] = __float2half_rn(W_enc[r]);
    } else if (idx < N0 + N1 + N2) {
        int r = idx - N0 - N1;
        int row = r / PCOL, col = r % PCOL;
        Wout_r[r] = tf32r(W_out[(size_t)row * (HH + DENC + EE) + col]);
    }
}

// fp32 -> fp16 bulk convert (4 elems/thread)
__global__ void cvt_f16_kernel(const float* __restrict__ in,
                               __half* __restrict__ out, int n4) {
    int i = blockIdx.x * blockDim.x + threadIdx.x;
    if (i < n4) {
        float4 v = ((const float4*)in)[i];
        ((__half2*)out)[2 * i] = __floats2half2_rn(v.x, v.y);
        ((__half2*)out)[2 * i + 1] = __floats2half2_rn(v.z, v.w);
    }
}

__global__ void init_state_kernel(const float* __restrict__ h0,
                                  const float* __restrict__ c0,
                                  float* __restrict__ xbuf,
                                  float* __restrict__ x1buf,
                                  float* __restrict__ cb0,
                                  float* __restrict__ cb1) {
    int idx = blockIdx.x * blockDim.x + threadIdx.x;  // B*H
    int b = idx >> 9;
    int h = idx & (HH - 1);
    xbuf[(size_t)b * (DENC + HH) + DENC + h] = tf32r(h0[idx]);
    x1buf[(size_t)b * (HH + HH) + HH + h] = tf32r(h0[(size_t)BB * HH + idx]);
    cb0[idx] = c0[idx];
    cb1[idx] = c0[(size_t)BB * HH + idx];
}

// ---------------- attention (fused score/tanh + masked softmax + context) ----------------
__global__ void __launch_bounds__(256) attention_kernel(
    const __half* __restrict__ enc_proj,   // (B,S,H) fp16
    const __half* __restrict__ enc,        // (B,S,DENC) fp16
    const float* __restrict__ decp,        // (B,H)
    const float* __restrict__ vvec,        // (H)
    const int* __restrict__ mask,          // (B,S)
    float* __restrict__ ctx_dst1, int ld1,
    float* __restrict__ ctx_dst2, int ld2) {
    const int b = blockIdx.x;
    __shared__ float s_dp[HH];
    __shared__ float s_v[HH];
    __shared__ float s_w[SS];
    __shared__ float s_red[2];
    const int tid = threadIdx.x;
    const int warp = tid >> 5, lane = tid & 31;

    for (int i = tid; i < HH; i += 256) {
        s_dp[i] = decp[(size_t)b * HH + i];
        s_v[i] = vvec[i];
    }
    __syncthreads();

    for (int s = warp; s < SS; s += 8) {
        const __half2* ep = (const __half2*)(enc_proj + ((size_t)b * SS + s) * HH);
        float acc = 0.0f;
#pragma unroll 4
        for (int h2 = lane; h2 < HH / 2; h2 += 32) {
            float2 e = __half22float2(ep[h2]);
            acc += s_v[2 * h2] * tanh_hw(s_dp[2 * h2] + e.x);
            acc += s_v[2 * h2 + 1] * tanh_hw(s_dp[2 * h2 + 1] + e.y);
        }
#pragma unroll
        for (int o = 16; o; o >>= 1) acc += __shfl_xor_sync(0xffffffffu, acc, o);
        if (lane == 0) s_w[s] = mask[b * SS + s] ? acc : -1e30f;
    }
    __syncthreads();

    if (warp == 0) {
        float m = fmaxf(s_w[lane], s_w[lane + 32]);
#pragma unroll
        for (int o = 16; o; o >>= 1) m = fmaxf(m, __shfl_xor_sync(0xffffffffu, m, o));
        float sum = __expf(s_w[lane] - m) + __expf(s_w[lane + 32] - m);
#pragma unroll
        for (int o = 16; o; o >>= 1) sum += __shfl_xor_sync(0xffffffffu, sum, o);
        if (lane == 0) { s_red[0] = m; s_red[1] = sum; }
    }
    __syncthreads();
    const float m = s_red[0], inv = 1.0f / s_red[1];
    if (tid < SS) s_w[tid] = __expf(s_w[tid] - m) * inv;
    __syncthreads();

    // context: thread tid owns 4 d-elems (fp16 source, fp32 accum)
    const __half2* eb2 = (const __half2*)(enc + (size_t)b * SS * DENC);
    float4 acc4 = make_float4(0.f, 0.f, 0.f, 0.f);
#pragma unroll 8
    for (int s = 0; s < SS; s++) {
        const float w = s_w[s];
        uint2 raw = *(const uint2*)(eb2 + (size_t)s * (DENC / 2) + 2 * tid);
        float2 e01 = __half22float2(*(const __half2*)&raw.x);
        float2 e23 = __half22float2(*(const __half2*)&raw.y);
        acc4.x += w * e01.x; acc4.y += w * e01.y;
        acc4.z += w * e23.x; acc4.w += w * e23.y;
    }
    acc4.x = tf32r(acc4.x); acc4.y = tf32r(acc4.y);
    acc4.z = tf32r(acc4.z); acc4.w = tf32r(acc4.w);
    *(float4*)(ctx_dst1 + (size_t)b * ld1 + 4 * tid) = acc4;
    *(float4*)(ctx_dst2 + (size_t)b * ld2 + 4 * tid) = acc4;
}

// ---------------- LSTM pointwise cell (vectorized, plain gate layout) ----------------
__global__ void lstm_cell_kernel(const float* __restrict__ gates,  // (B,4H)
                                 float* __restrict__ c,            // (B,H) in/out
                                 float* __restrict__ hA, int ldA,
                                 float* __restrict__ hB, int ldB) {
    int idx = blockIdx.x * blockDim.x + threadIdx.x;  // B*H/4
    int b = idx / (HH / 4);
    int q = idx % (HH / 4);
    const float* gp = gates + (size_t)b * G4H + 4 * q;
    float4 gi = *(const float4*)(gp);
    float4 gf = *(const float4*)(gp + HH);
    float4 gg = *(const float4*)(gp + 2 * HH);
    float4 go = *(const float4*)(gp + 3 * HH);
    float4 cc = *(float4*)(c + (size_t)b * HH + 4 * q);
    float4 cn, hn;
    cn.x = sigmoid_fast(gf.x) * cc.x + sigmoid_fast(gi.x) * tanhf(gg.x);
    cn.y = sigmoid_fast(gf.y) * cc.y + sigmoid_fast(gi.y) * tanhf(gg.y);
    cn.z = sigmoid_fast(gf.z) * cc.z + sigmoid_fast(gi.z) * tanhf(gg.z);
    cn.w = sigmoid_fast(gf.w) * cc.w + sigmoid_fast(gi.w) * tanhf(gg.w);
    hn.x = tf32r(sigmoid_fast(go.x) * tanhf(cn.x));
    hn.y = tf32r(sigmoid_fast(go.y) * tanhf(cn.y));
    hn.z = tf32r(sigmoid_fast(go.z) * tanhf(cn.z));
    hn.w = tf32r(sigmoid_fast(go.w) * tanhf(cn.w));
    *(float4*)(c + (size_t)b * HH + 4 * q) = cn;
    *(float4*)(hA + (size_t)b * ldA + 4 * q) = hn;
    *(float4*)(hB + (size_t)b * ldB + 4 * q) = hn;
}

// ---------------- host ----------------
extern "C" void kernel_launch(void* const* d_in, const int* in_sizes, int n_in,
                              void* d_out, int out_size) {
    const float* encoder_out = (const float*)d_in[0];
    const float* h0   = (const float*)d_in[1];
    const float* c0   = (const float*)d_in[2];
    const int*   targets = (const int*)d_in[3];
    const int*   mask    = (const int*)d_in[4];
    const float* emb   = (const float*)d_in[5];
    const float* W_enc = (const float*)d_in[6];
    const float* W_dec = (const float*)d_in[7];
    const float* vvec  = (const float*)d_in[8];
    const float* W_ih0 = (const float*)d_in[9];
    const float* W_hh0 = (const float*)d_in[10];
    const float* b_ih0 = (const float*)d_in[11];
    const float* b_hh0 = (const float*)d_in[12];
    const float* W_ih1 = (const float*)d_in[13];
    const float* W_hh1 = (const float*)d_in[14];
    const float* b_ih1 = (const float*)d_in[15];
    const float* b_hh1 = (const float*)d_in[16];
    const float* W_out = (const float*)d_in[17];
    const float* b_out = (const float*)d_in[18];
    float* out = (float*)d_out;  // (B,T,V)

    __half *p_encproj_h, *p_enc_h, *p_Wenc_h;
    float *p_pred, *p_Wc0, *p_Wc1, *p_Wdec, *p_Wout, *p_tokg, *p_tokp;
    float *p_xbuf, *p_x1buf, *p_gates, *p_c0, *p_c1, *p_decproj;
    int* p_tokens;
    cudaGetSymbolAddress((void**)&p_encproj_h, g_encproj_h);
    cudaGetSymbolAddress((void**)&p_enc_h, g_enc_h);
    cudaGetSymbolAddress((void**)&p_Wenc_h, g_Wenc_h);
    cudaGetSymbolAddress((void**)&p_pred, g_pred);
    cudaGetSymbolAddress((void**)&p_Wc0, g_Wc0);
    cudaGetSymbolAddress((void**)&p_Wc1, g_Wc1);
    cudaGetSymbolAddress((void**)&p_Wdec, g_Wdec_r);
    cudaGetSymbolAddress((void**)&p_Wout, g_Wout_r);
    cudaGetSymbolAddress((void**)&p_tokg, g_token_gates);
    cudaGetSymbolAddress((void**)&p_tokp, g_token_preds);
    cudaGetSymbolAddress((void**)&p_tokens, g_tokens);
    cudaGetSymbolAddress((void**)&p_xbuf, g_xbuf);
    cudaGetSymbolAddress((void**)&p_x1buf, g_x1buf);
    cudaGetSymbolAddress((void**)&p_gates, g_gates);
    cudaGetSymbolAddress((void**)&p_c0, g_c0buf);
    cudaGetSymbolAddress((void**)&p_c1, g_c1buf);
    cudaGetSymbolAddress((void**)&p_decproj, g_decproj);

    // ---- precompute ----
    tokens_kernel<<<(BB * TT) / 256, 256>>>(targets, p_tokens);
    {
        int total = G4H * (DENC + HH) + G4H * (HH + HH);
        build_wcomb_kernel<<<(total + 255) / 256, 256>>>(W_ih0, W_hh0, W_ih1, W_hh1,
                                                         p_Wc0, p_Wc1);
    }
    {
        int total = HH * HH + HH * DENC + VV * PCOL;
        round_weights_kernel<<<(total + 255) / 256, 256>>>(W_dec, W_enc, W_out,
                                                           p_Wdec, p_Wenc_h, p_Wout);
    }
    {
        int n4 = (BB * SS * DENC) / 4;
        cvt_f16_kernel<<<(n4 + 255) / 256, 256>>>(encoder_out, p_enc_h, n4);
    }
    init_state_kernel<<<(BB * HH) / 256, 256>>>(h0, c0, p_xbuf, p_x1buf, p_c0, p_c1);

    // token_gates (V,4H) = emb @ W_ih0[:, :E]^T   (raw operands)
    mgemm<64, 128, 16, 32, 64, 4, false, false>(VV, G4H, EE, emb, EE, W_ih0, EE + DENC,
                                                p_tokg, G4H);
    // token_preds (V,V) = emb @ W_out[:, H+DENC:]^T + b_out
    mgemm<64, 64, 16, 32, 32, 4, false, false>(VV, VV, EE, emb, EE,
                                               W_out + (HH + DENC), HH + DENC + EE,
                                               p_tokp, VV, nullptr, 0, b_out);
    // enc_proj -> fp16 (score path only): fp16 tensor-core GEMM
    {
        dim3 grid(HH / 128, (BB * SS) / 128);
        mma_nt_f16_kernel<128, 128, 32, 64, 32, 3><<<grid, 256>>>(
            BB * SS, HH, DENC, p_enc_h, DENC, p_Wenc_h, DENC, p_encproj_h, HH);
    }

    // ---- sequential decode ----
    for (int t = 0; t < TT; t++) {
        // dec_proj = h1 @ Wdec_r^T   (pre-rounded operands)
        mgemm<64, 64, 16, 32, 32, 4, true, true>(BB, HH, HH, p_x1buf + HH, HH + HH,
                                                 p_Wdec, HH, p_decproj, HH);

        // attention: context -> xbuf[:, :DENC] and pred[:, t, H:]
        attention_kernel<<<BB, 256>>>(p_encproj_h, p_enc_h, p_decproj, vvec, mask,
                                      p_xbuf, DENC + HH,
                                      p_pred + (size_t)t * PCOL + HH, TT * PCOL);

        // gates0 = [context|h0] @ Wc0^T + token_gates[tok(b,t)] + b_ih0 + b_hh0
        mgemm<64, 128, 16, 32, 64, 4, true, true>(BB, G4H, DENC + HH, p_xbuf, DENC + HH,
                                                  p_Wc0, DENC + HH, p_gates, G4H,
                                                  p_tokg, G4H, b_ih0, b_hh0,
                                                  p_tokens + t, TT);
        lstm_cell_kernel<<<(BB * HH / 4) / 256, 256>>>(p_gates, p_c0,
                                                       p_x1buf, HH + HH,
                                                       p_xbuf + DENC, DENC + HH);

        // gates1 = [h0n|h1] @ Wc1^T + b_ih1 + b_hh1
        mgemm<64, 128, 16, 32, 64, 4, true, true>(BB, G4H, HH + HH, p_x1buf, HH + HH,
                                                  p_Wc1, HH + HH, p_gates, G4H,
                                                  nullptr, 0, b_ih1, b_hh1);
        lstm_cell_kernel<<<(BB * HH / 4) / 256, 256>>>(p_gates, p_c1,
                                                       p_x1buf + HH, HH + HH,
                                                       p_pred + (size_t)t * PCOL, TT * PCOL);
    }

    // logits: out = [h1n|context] @ Wout_r^T + token_preds[tok(b,t)]  (BM64: 256 CTAs)
    mgemm<64, 128, 16, 32, 64, 4, true, true>(BB * TT, VV, PCOL, p_pred, PCOL,
                                              p_Wout, PCOL, out, VV,
                                              p_tokp, VV, nullptr, nullptr,
                                              p_tokens, 1);
}

// round 14
// speedup vs baseline: 1.5803x; 1.4307x over previous
#include <cuda_runtime.h>
#include <cuda_fp16.h>
#include <math.h>
#include <stdint.h>

#define BB 512
#define SS 64
#define TT 32
#define VV 128
#define EE 256
#define HH 512
#define DENC 1024
#define G4H 2048
#define EOS_IDX 2
#define PCOL (HH + DENC)  /* 1536 */

// ---------------- scratch (device globals; no allocations) ----------------
__device__ __half g_encproj_h[(size_t)BB * SS * HH];   // 32 MB (score path)
__device__ __half g_enc_h[(size_t)BB * SS * DENC];     // 64 MB (attention + enc_proj A)
__device__ __half g_Wenc_h[HH * DENC];
__device__ __half g_pred[(size_t)BB * TT * PCOL];      // 50 MB [h1n | context] fp16
__device__ __half g_Wc0[G4H * (DENC + HH)];            // fp16 [W_ih0[:,E:] | W_hh0]
__device__ __half g_Wc1[G4H * (HH + HH)];              // fp16 [W_ih1 | W_hh1]
__device__ __half g_Wdec_h[HH * HH];
__device__ __half g_Wout_h[VV * PCOL];                 // compact W_out[:, :PCOL]
__device__ float g_token_gates[VV * G4H];              // per-token gates add (fp32 Cin)
__device__ float g_token_preds[VV * VV];               // per-token logits add (fp32 Cin)
__device__ int   g_tokens[BB * TT];
__device__ __half g_xbuf[BB * (DENC + HH)];            // [context | h0] fp16
__device__ __half g_x1buf[BB * (HH + HH)];             // [h0n | h1] fp16
__device__ float g_gates[BB * G4H];
__device__ float g_c0buf[BB * HH];
__device__ float g_c1buf[BB * HH];
__device__ float g_decproj[BB * HH];

__device__ __forceinline__ float sigmoid_fast(float x) {
    return __fdividef(1.0f, 1.0f + __expf(-x));
}
__device__ __forceinline__ float tanh_hw(float x) {
    float y;
    asm("tanh.approx.f32 %0, %1;" : "=f"(y) : "f"(x));
    return y;
}
__device__ __forceinline__ uint32_t f2tf32(float x) {
    uint32_t r;
    asm("cvt.rna.tf32.f32 %0, %1;" : "=r"(r) : "f"(x));
    return r;
}
__device__ __forceinline__ float tf32r(float x) { return __uint_as_float(f2tf32(x)); }

__device__ __forceinline__ uint32_t smem_u32(const void* p) {
    return (uint32_t)__cvta_generic_to_shared(p);
}
__device__ __forceinline__ void cp_async16(void* smem, const void* gmem) {
    asm volatile("cp.async.cg.shared.global [%0], [%1], 16;"
                 :: "r"(smem_u32(smem)), "l"(gmem));
}
__device__ __forceinline__ void cp_commit() {
    asm volatile("cp.async.commit_group;");
}
template <int N>
__device__ __forceinline__ void cp_wait() {
    asm volatile("cp.async.wait_group %0;" :: "n"(N));
}

__device__ __forceinline__ void mma_tf32(float* c, const uint32_t* a, const uint32_t* b) {
    asm volatile(
        "mma.sync.aligned.m16n8k8.row.col.f32.tf32.tf32.f32 "
        "{%0,%1,%2,%3},{%4,%5,%6,%7},{%8,%9},{%0,%1,%2,%3};"
        : "+f"(c[0]), "+f"(c[1]), "+f"(c[2]), "+f"(c[3])
        : "r"(a[0]), "r"(a[1]), "r"(a[2]), "r"(a[3]), "r"(b[0]), "r"(b[1]));
}
__device__ __forceinline__ void mma_f16(float* c, const uint32_t* a, const uint32_t* b) {
    asm volatile(
        "mma.sync.aligned.m16n8k16.row.col.f32.f16.f16.f32 "
        "{%0,%1,%2,%3},{%4,%5,%6,%7},{%8,%9},{%0,%1,%2,%3};"
        : "+f"(c[0]), "+f"(c[1]), "+f"(c[2]), "+f"(c[3])
        : "r"(a[0]), "r"(a[1]), "r"(a[2]), "r"(a[3]), "r"(b[0]), "r"(b[1]));
}

// ---------------- TF32 NT GEMM (precompute only: token_gates / token_preds) ----------
template <int BM, int BN, int BK, int WM, int WN, int STAGES>
__global__ void __launch_bounds__((BM / WM) * (BN / WN) * 32, 2)
mma_nt_kernel(int M, int N, int K,
              const float* __restrict__ A, int lda,
              const float* __restrict__ B, int ldb,
              float* __restrict__ C, int ldc,
              const float* __restrict__ bias0) {
    constexpr int WARPS_M = BM / WM, WARPS_N = BN / WN;
    constexpr int NW = WARPS_M * WARPS_N, THREADS = NW * 32;
    constexpr int MI = WM / 16, NI = WN / 8, KI = BK / 8;
    constexpr int LDS_ = BK + 4;
    constexpr int A_CP = BM * (BK / 4) / THREADS;
    constexpr int B_CP = BN * (BK / 4) / THREADS;

    __shared__ __align__(16) float As[STAGES][BM][LDS_];
    __shared__ __align__(16) float Bs[STAGES][BN][LDS_];

    const int tid = threadIdx.x;
    const int wid = tid >> 5, lane = tid & 31;
    const int wm = (wid / WARPS_N) * WM, wn = (wid % WARPS_N) * WN;
    const int g = lane >> 2, tg = lane & 3;
    const int bm = blockIdx.y * BM, bn = blockIdx.x * BN;

    float acc[MI][NI][4];
#pragma unroll
    for (int i = 0; i < MI; i++)
#pragma unroll
        for (int j = 0; j < NI; j++)
#pragma unroll
            for (int q = 0; q < 4; q++) acc[i][j][q] = 0.0f;

    auto issue_tile = [&](int tile, int slot) {
        const int k0 = tile * BK;
#pragma unroll
        for (int i = 0; i < A_CP; i++) {
            int idx = tid + i * THREADS;
            int m = idx / (BK / 4), kq = (idx % (BK / 4)) * 4;
            cp_async16(&As[slot][m][kq], A + (size_t)(bm + m) * lda + k0 + kq);
        }
#pragma unroll
        for (int i = 0; i < B_CP; i++) {
            int idx = tid + i * THREADS;
            int n = idx / (BK / 4), kq = (idx % (BK / 4)) * 4;
            cp_async16(&Bs[slot][n][kq], B + (size_t)(bn + n) * ldb + k0 + kq);
        }
    };

    const int ntiles = K / BK;
#pragma unroll
    for (int s = 0; s < STAGES - 1; s++) {
        issue_tile(s, s);
        cp_commit();
    }

    for (int t = 0; t < ntiles; t++) {
        cp_wait<STAGES - 2>();
        __syncthreads();
        const int slot = t % STAGES;
#pragma unroll
        for (int ki = 0; ki < KI; ki++) {
            const int k_lo = ki * 8 + tg, k_hi = k_lo + 4;
            uint32_t af[MI][4];
            uint32_t bfv[NI][2];
#pragma unroll
            for (int mi = 0; mi < MI; mi++) {
                const int mr = wm + mi * 16 + g;
                af[mi][0] = f2tf32(As[slot][mr][k_lo]);
                af[mi][1] = f2tf32(As[slot][mr + 8][k_lo]);
                af[mi][2] = f2tf32(As[slot][mr][k_hi]);
                af[mi][3] = f2tf32(As[slot][mr + 8][k_hi]);
            }
#pragma unroll
            for (int ni = 0; ni < NI; ni++) {
                const int nr = wn + ni * 8 + g;
                bfv[ni][0] = f2tf32(Bs[slot][nr][k_lo]);
                bfv[ni][1] = f2tf32(Bs[slot][nr][k_hi]);
            }
#pragma unroll
            for (int mi = 0; mi < MI; mi++)
#pragma unroll
                for (int ni = 0; ni < NI; ni++) mma_tf32(acc[mi][ni], af[mi], bfv[ni]);
        }
        if (t + STAGES - 1 < ntiles) issue_tile(t + STAGES - 1, (t + STAGES - 1) % STAGES);
        cp_commit();
    }

#pragma unroll
    for (int mi = 0; mi < MI; mi++) {
#pragma unroll
        for (int ni = 0; ni < NI; ni++) {
            const int col = bn + wn + ni * 8 + tg * 2;
#pragma unroll
            for (int half = 0; half < 2; half++) {
                const int row = bm + wm + mi * 16 + g + half * 8;
                float v0 = acc[mi][ni][half * 2 + 0];
                float v1 = acc[mi][ni][half * 2 + 1];
                if (bias0) { v0 += bias0[col]; v1 += bias0[col + 1]; }
                *(float2*)(C + (size_t)row * ldc + col) = make_float2(v0, v1);
            }
        }
    }
}

// ---------------- FP16 NT GEMM (m16n8k16), full epilogue ----------------
// C = A(MxK,h) * B(NxK,h)^T; out fp32 (+bias0+bias1+Cin[rowtok]) or fp16.
template <int BM, int BN, int BK, int WM, int WN, int STAGES>
__global__ void __launch_bounds__((BM / WM) * (BN / WN) * 32, 2)
hgemm_nt_kernel(int M, int N, int K,
                const __half* __restrict__ A, int lda,
                const __half* __restrict__ B, int ldb,
                void* __restrict__ Cv, int ldc,
                const float* __restrict__ Cin, int ldcin,
                const float* __restrict__ bias0,
                const float* __restrict__ bias1,
                const int* __restrict__ rowtok, int rts,
                int out_f16) {
    constexpr int WARPS_M = BM / WM, WARPS_N = BN / WN;
    constexpr int NW = WARPS_M * WARPS_N, THREADS = NW * 32;
    constexpr int MI = WM / 16, NI = WN / 8, KI = BK / 16;
    constexpr int LDS_ = BK + 8;  // halves; 80B row stride -> conflict-free frags
    constexpr int A_CP = BM * (BK / 8) / THREADS;
    constexpr int B_CP = BN * (BK / 8) / THREADS;

    __shared__ __align__(16) __half As[STAGES][BM][LDS_];
    __shared__ __align__(16) __half Bs[STAGES][BN][LDS_];

    const int tid = threadIdx.x;
    const int wid = tid >> 5, lane = tid & 31;
    const int wm = (wid / WARPS_N) * WM, wn = (wid % WARPS_N) * WN;
    const int g = lane >> 2, tg = lane & 3;
    const int bm = blockIdx.y * BM, bn = blockIdx.x * BN;

    float acc[MI][NI][4];
#pragma unroll
    for (int i = 0; i < MI; i++)
#pragma unroll
        for (int j = 0; j < NI; j++)
#pragma unroll
            for (int q = 0; q < 4; q++) acc[i][j][q] = 0.0f;

    auto issue_tile = [&](int tile, int slot) {
        const int k0 = tile * BK;
#pragma unroll
        for (int i = 0; i < A_CP; i++) {
            int idx = tid + i * THREADS;
            int m = idx / (BK / 8), kq = (idx % (BK / 8)) * 8;
            cp_async16(&As[slot][m][kq], A + (size_t)(bm + m) * lda + k0 + kq);
        }
#pragma unroll
        for (int i = 0; i < B_CP; i++) {
            int idx = tid + i * THREADS;
            int n = idx / (BK / 8), kq = (idx % (BK / 8)) * 8;
            cp_async16(&Bs[slot][n][kq], B + (size_t)(bn + n) * ldb + k0 + kq);
        }
    };

    const int ntiles = K / BK;
#pragma unroll
    for (int s = 0; s < STAGES - 1; s++) {
        issue_tile(s, s);
        cp_commit();
    }

    for (int t = 0; t < ntiles; t++) {
        cp_wait<STAGES - 2>();
        __syncthreads();
        const int slot = t % STAGES;

#pragma unroll
        for (int ki = 0; ki < KI; ki++) {
            const int kb = ki * 16 + tg * 2;
            uint32_t af[MI][4];
            uint32_t bfv[NI][2];
#pragma unroll
            for (int mi = 0; mi < MI; mi++) {
                const int mr = wm + mi * 16 + g;
                af[mi][0] = *(const uint32_t*)&As[slot][mr][kb];
                af[mi][1] = *(const uint32_t*)&As[slot][mr + 8][kb];
                af[mi][2] = *(const uint32_t*)&As[slot][mr][kb + 8];
                af[mi][3] = *(const uint32_t*)&As[slot][mr + 8][kb + 8];
            }
#pragma unroll
            for (int ni = 0; ni < NI; ni++) {
                const int nr = wn + ni * 8 + g;
                bfv[ni][0] = *(const uint32_t*)&Bs[slot][nr][kb];
                bfv[ni][1] = *(const uint32_t*)&Bs[slot][nr][kb + 8];
            }
#pragma unroll
            for (int mi = 0; mi < MI; mi++)
#pragma unroll
                for (int ni = 0; ni < NI; ni++) mma_f16(acc[mi][ni], af[mi], bfv[ni]);
        }

        if (t + STAGES - 1 < ntiles) issue_tile(t + STAGES - 1, (t + STAGES - 1) % STAGES);
        cp_commit();
    }

#pragma unroll
    for (int mi = 0; mi < MI; mi++) {
#pragma unroll
        for (int ni = 0; ni < NI; ni++) {
            const int col = bn + wn + ni * 8 + tg * 2;
#pragma unroll
            for (int half = 0; half < 2; half++) {
                const int row = bm + wm + mi * 16 + g + half * 8;
                float v0 = acc[mi][ni][half * 2 + 0];
                float v1 = acc[mi][ni][half * 2 + 1];
                if (out_f16) {
                    __half2* cp = (__half2*)((__half*)Cv + (size_t)row * ldc + col);
                    *cp = __floats2half2_rn(v0, v1);
                    continue;
                }
                float* C = (float*)Cv;
                if (bias0) { v0 += bias0[col]; v1 += bias0[col + 1]; }
                if (bias1) { v0 += bias1[col]; v1 += bias1[col + 1]; }
                if (Cin) {
                    const int crow = rowtok ? rowtok[row * rts] : row;
                    float2 ci = *(const float2*)(Cin + (size_t)crow * ldcin + col);
                    v0 += ci.x; v1 += ci.y;
                }
                *(float2*)(C + (size_t)row * ldc + col) = make_float2(v0, v1);
            }
        }
    }
}

template <int BM, int BN, int BK, int WM, int WN, int STAGES>
static void hgemm(int M, int N, int K,
                  const __half* A, int lda, const __half* B, int ldb,
                  void* C, int ldc,
                  const float* Cin = nullptr, int ldcin = 0,
                  const float* bias0 = nullptr, const float* bias1 = nullptr,
                  const int* rowtok = nullptr, int rts = 1,
                  bool out_f16 = false) {
    dim3 grid(N / BN, M / BM);
    hgemm_nt_kernel<BM, BN, BK, WM, WN, STAGES>
        <<<grid, (BM / WM) * (BN / WN) * 32>>>(
            M, N, K, A, lda, B, ldb, C, ldc, Cin, ldcin, bias0, bias1, rowtok, rts,
            out_f16 ? 1 : 0);
}

// ---------------- precompute kernels ----------------
__global__ void tokens_kernel(const int* __restrict__ targets, int* __restrict__ toks) {
    int idx = blockIdx.x * blockDim.x + threadIdx.x;  // B*T
    int t = idx & (TT - 1);
    int b = idx >> 5;
    toks[idx] = (t == 0) ? EOS_IDX : targets[b * TT + t - 1];
}

// combined weights -> fp16
__global__ void build_wcomb_kernel(const float* __restrict__ W_ih0,
                                   const float* __restrict__ W_hh0,
                                   const float* __restrict__ W_ih1,
                                   const float* __restrict__ W_hh1,
                                   __half* __restrict__ Wc0,
                                   __half* __restrict__ Wc1) {
    int idx = blockIdx.x * blockDim.x + threadIdx.x;
    const int N0 = G4H * (DENC + HH);
    const int N1 = G4H * (HH + HH);
    if (idx < N0) {
        int n = idx / (DENC + HH);
        int k = idx % (DENC + HH);
        float v = (k < DENC) ? W_ih0[(size_t)n * (EE + DENC) + EE + k]
                             : W_hh0[(size_t)n * HH + (k - DENC)];
        Wc0[idx] = __float2half_rn(v);
    } else if (idx < N0 + N1) {
        int r = idx - N0;
        int n = r / (HH + HH);
        int k = r % (HH + HH);
        float v = (k < HH) ? W_ih1[(size_t)n * HH + k]
                           : W_hh1[(size_t)n * HH + (k - HH)];
        Wc1[r] = __float2half_rn(v);
    }
}

// fp16 copies of W_dec, W_enc, compact W_out[:, :PCOL]
__global__ void round_weights_kernel(const float* __restrict__ W_dec,
                                     const float* __restrict__ W_enc,
                                     const float* __restrict__ W_out,
                                     __half* __restrict__ Wdec_h,
                                     __half* __restrict__ Wenc_h,
                                     __half* __restrict__ Wout_h) {
    int idx = blockIdx.x * blockDim.x + threadIdx.x;
    const int N0 = HH * HH;
    const int N1 = HH * DENC;
    const int N2 = VV * PCOL;
    if (idx < N0) {
        Wdec_h[idx] = __float2half_rn(W_dec[idx]);
    } else if (idx < N0 + N1) {
        int r = idx - N0;
        Wenc_h[r] = __float2half_rn(W_enc[r]);
    } else if (idx < N0 + N1 + N2) {
        int r = idx - N0 - N1;
        int row = r / PCOL, col = r % PCOL;
        Wout_h[r] = __float2half_rn(W_out[(size_t)row * (HH + DENC + EE) + col]);
    }
}

// fp32 -> fp16 bulk convert (4 elems/thread)
__global__ void cvt_f16_kernel(const float* __restrict__ in,
                               __half* __restrict__ out, int n4) {
    int i = blockIdx.x * blockDim.x + threadIdx.x;
    if (i < n4) {
        float4 v = ((const float4*)in)[i];
        ((__half2*)out)[2 * i] = __floats2half2_rn(v.x, v.y);
        ((__half2*)out)[2 * i + 1] = __floats2half2_rn(v.z, v.w);
    }
}

__global__ void init_state_kernel(const float* __restrict__ h0,
                                  const float* __restrict__ c0,
                                  __half* __restrict__ xbuf,
                                  __half* __restrict__ x1buf,
                                  float* __restrict__ cb0,
                                  float* __restrict__ cb1) {
    int idx = blockIdx.x * blockDim.x + threadIdx.x;  // B*H
    int b = idx >> 9;
    int h = idx & (HH - 1);
    xbuf[(size_t)b * (DENC + HH) + DENC + h] = __float2half_rn(h0[idx]);
    x1buf[(size_t)b * (HH + HH) + HH + h] = __float2half_rn(h0[(size_t)BB * HH + idx]);
    cb0[idx] = c0[idx];
    cb1[idx] = c0[(size_t)BB * HH + idx];
}

// ---------------- attention (fused score/tanh + masked softmax + context) ----------------
__global__ void __launch_bounds__(256) attention_kernel(
    const __half* __restrict__ enc_proj,   // (B,S,H) fp16
    const __half* __restrict__ enc,        // (B,S,DENC) fp16
    const float* __restrict__ decp,        // (B,H)
    const float* __restrict__ vvec,        // (H)
    const int* __restrict__ mask,          // (B,S)
    __half* __restrict__ ctx_dst1, int ld1,
    __half* __restrict__ ctx_dst2, int ld2) {
    const int b = blockIdx.x;
    __shared__ float s_dp[HH];
    __shared__ float s_v[HH];
    __shared__ float s_w[SS];
    __shared__ float s_red[2];
    const int tid = threadIdx.x;
    const int warp = tid >> 5, lane = tid & 31;

    for (int i = tid; i < HH; i += 256) {
        s_dp[i] = decp[(size_t)b * HH + i];
        s_v[i] = vvec[i];
    }
    __syncthreads();

    for (int s = warp; s < SS; s += 8) {
        const __half2* ep = (const __half2*)(enc_proj + ((size_t)b * SS + s) * HH);
        float acc = 0.0f;
#pragma unroll 4
        for (int h2 = lane; h2 < HH / 2; h2 += 32) {
            float2 e = __half22float2(ep[h2]);
            acc += s_v[2 * h2] * tanh_hw(s_dp[2 * h2] + e.x);
            acc += s_v[2 * h2 + 1] * tanh_hw(s_dp[2 * h2 + 1] + e.y);
        }
#pragma unroll
        for (int o = 16; o; o >>= 1) acc += __shfl_xor_sync(0xffffffffu, acc, o);
        if (lane == 0) s_w[s] = mask[b * SS + s] ? acc : -1e30f;
    }
    __syncthreads();

    if (warp == 0) {
        float m = fmaxf(s_w[lane], s_w[lane + 32]);
#pragma unroll
        for (int o = 16; o; o >>= 1) m = fmaxf(m, __shfl_xor_sync(0xffffffffu, m, o));
        float sum = __expf(s_w[lane] - m) + __expf(s_w[lane + 32] - m);
#pragma unroll
        for (int o = 16; o; o >>= 1) sum += __shfl_xor_sync(0xffffffffu, sum, o);
        if (lane == 0) { s_red[0] = m; s_red[1] = sum; }
    }
    __syncthreads();
    const float m = s_red[0], inv = 1.0f / s_red[1];
    if (tid < SS) s_w[tid] = __expf(s_w[tid] - m) * inv;
    __syncthreads();

    // context: thread tid owns 4 d-elems; fp32 accum, fp16 store
    const __half2* eb2 = (const __half2*)(enc + (size_t)b * SS * DENC);
    float4 acc4 = make_float4(0.f, 0.f, 0.f, 0.f);
#pragma unroll 8
    for (int s = 0; s < SS; s++) {
        const float w = s_w[s];
        uint2 raw = *(const uint2*)(eb2 + (size_t)s * (DENC / 2) + 2 * tid);
        float2 e01 = __half22float2(*(const __half2*)&raw.x);
        float2 e23 = __half22float2(*(const __half2*)&raw.y);
        acc4.x += w * e01.x; acc4.y += w * e01.y;
        acc4.z += w * e23.x; acc4.w += w * e23.y;
    }
    __half2 c01 = __floats2half2_rn(acc4.x, acc4.y);
    __half2 c23 = __floats2half2_rn(acc4.z, acc4.w);
    *(__half2*)(ctx_dst1 + (size_t)b * ld1 + 4 * tid) = c01;
    *(__half2*)(ctx_dst1 + (size_t)b * ld1 + 4 * tid + 2) = c23;
    *(__half2*)(ctx_dst2 + (size_t)b * ld2 + 4 * tid) = c01;
    *(__half2*)(ctx_dst2 + (size_t)b * ld2 + 4 * tid + 2) = c23;
}

// ---------------- LSTM pointwise cell (vectorized; fp16 h stores) ----------------
__global__ void lstm_cell_kernel(const float* __restrict__ gates,  // (B,4H)
                                 float* __restrict__ c,            // (B,H) in/out
                                 __half* __restrict__ hA, int ldA,
                                 __half* __restrict__ hB, int ldB) {
    int idx = blockIdx.x * blockDim.x + threadIdx.x;  // B*H/4
    int b = idx / (HH / 4);
    int q = idx % (HH / 4);
    const float* gp = gates + (size_t)b * G4H + 4 * q;
    float4 gi = *(const float4*)(gp);
    float4 gf = *(const float4*)(gp + HH);
    float4 gg = *(const float4*)(gp + 2 * HH);
    float4 go = *(const float4*)(gp + 3 * HH);
    float4 cc = *(float4*)(c + (size_t)b * HH + 4 * q);
    float4 cn;
    cn.x = sigmoid_fast(gf.x) * cc.x + sigmoid_fast(gi.x) * tanhf(gg.x);
    cn.y = sigmoid_fast(gf.y) * cc.y + sigmoid_fast(gi.y) * tanhf(gg.y);
    cn.z = sigmoid_fast(gf.z) * cc.z + sigmoid_fast(gi.z) * tanhf(gg.z);
    cn.w = sigmoid_fast(gf.w) * cc.w + sigmoid_fast(gi.w) * tanhf(gg.w);
    __half2 h01 = __floats2half2_rn(sigmoid_fast(go.x) * tanhf(cn.x),
                                    sigmoid_fast(go.y) * tanhf(cn.y));
    __half2 h23 = __floats2half2_rn(sigmoid_fast(go.z) * tanhf(cn.z),
                                    sigmoid_fast(go.w) * tanhf(cn.w));
    *(float4*)(c + (size_t)b * HH + 4 * q) = cn;
    *(__half2*)(hA + (size_t)b * ldA + 4 * q) = h01;
    *(__half2*)(hA + (size_t)b * ldA + 4 * q + 2) = h23;
    *(__half2*)(hB + (size_t)b * ldB + 4 * q) = h01;
    *(__half2*)(hB + (size_t)b * ldB + 4 * q + 2) = h23;
}

// ---------------- host ----------------
extern "C" void kernel_launch(void* const* d_in, const int* in_sizes, int n_in,
                              void* d_out, int out_size) {
    const float* encoder_out = (const float*)d_in[0];
    const float* h0   = (const float*)d_in[1];
    const float* c0   = (const float*)d_in[2];
    const int*   targets = (const int*)d_in[3];
    const int*   mask    = (const int*)d_in[4];
    const float* emb   = (const float*)d_in[5];
    const float* W_enc = (const float*)d_in[6];
    const float* W_dec = (const float*)d_in[7];
    const float* vvec  = (const float*)d_in[8];
    const float* W_ih0 = (const float*)d_in[9];
    const float* W_hh0 = (const float*)d_in[10];
    const float* b_ih0 = (const float*)d_in[11];
    const float* b_hh0 = (const float*)d_in[12];
    const float* W_ih1 = (const float*)d_in[13];
    const float* W_hh1 = (const float*)d_in[14];
    const float* b_ih1 = (const float*)d_in[15];
    const float* b_hh1 = (const float*)d_in[16];
    const float* W_out = (const float*)d_in[17];
    const float* b_out = (const float*)d_in[18];
    float* out = (float*)d_out;  // (B,T,V)

    __half *p_encproj_h, *p_enc_h, *p_Wenc_h, *p_pred, *p_Wc0, *p_Wc1, *p_Wdec, *p_Wout;
    __half *p_xbuf, *p_x1buf;
    float *p_tokg, *p_tokp, *p_gates, *p_c0, *p_c1, *p_decproj;
    int* p_tokens;
    cudaGetSymbolAddress((void**)&p_encproj_h, g_encproj_h);
    cudaGetSymbolAddress((void**)&p_enc_h, g_enc_h);
    cudaGetSymbolAddress((void**)&p_Wenc_h, g_Wenc_h);
    cudaGetSymbolAddress((void**)&p_pred, g_pred);
    cudaGetSymbolAddress((void**)&p_Wc0, g_Wc0);
    cudaGetSymbolAddress((void**)&p_Wc1, g_Wc1);
    cudaGetSymbolAddress((void**)&p_Wdec, g_Wdec_h);
    cudaGetSymbolAddress((void**)&p_Wout, g_Wout_h);
    cudaGetSymbolAddress((void**)&p_tokg, g_token_gates);
    cudaGetSymbolAddress((void**)&p_tokp, g_token_preds);
    cudaGetSymbolAddress((void**)&p_tokens, g_tokens);
    cudaGetSymbolAddress((void**)&p_xbuf, g_xbuf);
    cudaGetSymbolAddress((void**)&p_x1buf, g_x1buf);
    cudaGetSymbolAddress((void**)&p_gates, g_gates);
    cudaGetSymbolAddress((void**)&p_c0, g_c0buf);
    cudaGetSymbolAddress((void**)&p_c1, g_c1buf);
    cudaGetSymbolAddress((void**)&p_decproj, g_decproj);

    // ---- precompute ----
    tokens_kernel<<<(BB * TT) / 256, 256>>>(targets, p_tokens);
    {
        int total = G4H * (DENC + HH) + G4H * (HH + HH);
        build_wcomb_kernel<<<(total + 255) / 256, 256>>>(W_ih0, W_hh0, W_ih1, W_hh1,
                                                         p_Wc0, p_Wc1);
    }
    {
        int total = HH * HH + HH * DENC + VV * PCOL;
        round_weights_kernel<<<(total + 255) / 256, 256>>>(W_dec, W_enc, W_out,
                                                           p_Wdec, p_Wenc_h, p_Wout);
    }
    {
        int n4 = (BB * SS * DENC) / 4;
        cvt_f16_kernel<<<(n4 + 255) / 256, 256>>>(encoder_out, p_enc_h, n4);
    }
    init_state_kernel<<<(BB * HH) / 256, 256>>>(h0, c0, p_xbuf, p_x1buf, p_c0, p_c1);

    // token_gates (V,4H) = emb @ W_ih0[:, :E]^T  (tf32 path, raw fp32 operands)
    {
        dim3 grid(G4H / 128, VV / 64);
        mma_nt_kernel<64, 128, 16, 32, 64, 4><<<grid, 128>>>(
            VV, G4H, EE, emb, EE, W_ih0, EE + DENC, p_tokg, G4H, nullptr);
    }
    // token_preds (V,V) = emb @ W_out[:, H+DENC:]^T + b_out
    {
        dim3 grid(VV / 64, VV / 64);
        mma_nt_kernel<64, 64, 16, 32, 32, 4><<<grid, 128>>>(
            VV, VV, EE, emb, EE, W_out + (HH + DENC), HH + DENC + EE, p_tokp, VV, b_out);
    }
    // enc_proj -> fp16 (score path)
    hgemm<128, 128, 32, 64, 32, 3>(BB * SS, HH, DENC, p_enc_h, DENC, p_Wenc_h, DENC,
                                   p_encproj_h, HH, nullptr, 0, nullptr, nullptr,
                                   nullptr, 1, true);

    // ---- sequential decode ----
    for (int t = 0; t < TT; t++) {
        // dec_proj = h1 @ Wdec^T  (fp16)
        hgemm<64, 64, 32, 32, 32, 4>(BB, HH, HH, p_x1buf + HH, HH + HH, p_Wdec, HH,
                                     p_decproj, HH);

        // attention: context -> xbuf[:, :DENC] and pred[:, t, H:]
        attention_kernel<<<BB, 256>>>(p_encproj_h, p_enc_h, p_decproj, vvec, mask,
                                      p_xbuf, DENC + HH,
                                      p_pred + (size_t)t * PCOL + HH, TT * PCOL);

        // gates0 = [context|h0] @ Wc0^T + token_gates[tok(b,t)] + b_ih0 + b_hh0
        hgemm<64, 128, 32, 32, 64, 4>(BB, G4H, DENC + HH, p_xbuf, DENC + HH,
                                      p_Wc0, DENC + HH, p_gates, G4H,
                                      p_tokg, G4H, b_ih0, b_hh0,
                                      p_tokens + t, TT);
        lstm_cell_kernel<<<(BB * HH / 4) / 256, 256>>>(p_gates, p_c0,
                                                       p_x1buf, HH + HH,
                                                       p_xbuf + DENC, DENC + HH);

        // gates1 = [h0n|h1] @ Wc1^T + b_ih1 + b_hh1
        hgemm<64, 128, 32, 32, 64, 4>(BB, G4H, HH + HH, p_x1buf, HH + HH,
                                      p_Wc1, HH + HH, p_gates, G4H,
                                      nullptr, 0, b_ih1, b_hh1);
        lstm_cell_kernel<<<(BB * HH / 4) / 256, 256>>>(p_gates, p_c1,
                                                       p_x1buf + HH, HH + HH,
                                                       p_pred + (size_t)t * PCOL, TT * PCOL);
    }

    // logits: out = [h1n|context] @ Wout^T + token_preds[tok(b,t)]
    hgemm<64, 128, 32, 32, 64, 4>(BB * TT, VV, PCOL, p_pred, PCOL, p_Wout, PCOL,
                                  out, VV, p_tokp, VV, nullptr, nullptr,
                                  p_tokens, 1);
}

// round 15
// speedup vs baseline: 1.7964x; 1.1368x over previous
#include <cuda_runtime.h>
#include <cuda_fp16.h>
#include <math.h>
#include <stdint.h>

#define BB 512
#define SS 64
#define TT 32
#define VV 128
#define EE 256
#define HH 512
#define DENC 1024
#define G4H 2048
#define EOS_IDX 2
#define PCOL (HH + DENC)  /* 1536 */

// ---------------- scratch (device globals; no allocations) ----------------
__device__ __half g_encproj_h[(size_t)BB * SS * HH];   // 32 MB (score path)
__device__ __half g_enc_h[(size_t)BB * SS * DENC];     // 64 MB (attention + enc_proj A)
__device__ __half g_Wenc_h[HH * DENC];
__device__ __half g_pred[(size_t)BB * TT * PCOL];      // 50 MB [h1n | context] fp16
__device__ __half g_Wc0[G4H * (DENC + HH)];            // fp16 [W_ih0[:,E:] | W_hh0]
__device__ __half g_Wc1[G4H * (HH + HH)];              // fp16 [W_ih1 | W_hh1]
__device__ __half g_Wdec_h[HH * HH];
__device__ __half g_Wout_h[VV * PCOL];                 // compact W_out[:, :PCOL]
__device__ float g_token_gates[VV * G4H];              // per-token gates add (fp32 Cin)
__device__ float g_token_preds[VV * VV];               // per-token logits add (fp32 Cin)
__device__ float g_bsum0[G4H];                         // b_ih0 + b_hh0
__device__ float g_bsum1[G4H];                         // b_ih1 + b_hh1
__device__ int   g_tokens[BB * TT];
__device__ __half g_xbuf[BB * (DENC + HH)];            // [context | h0] fp16
__device__ __half g_x1buf[BB * (HH + HH)];             // [h0n | h1] fp16
__device__ float g_gates[BB * G4H];
__device__ float g_c0buf[BB * HH];
__device__ float g_c1buf[BB * HH];
__device__ float g_decproj[BB * HH];

__device__ __forceinline__ float sigmoid_fast(float x) {
    return __fdividef(1.0f, 1.0f + __expf(-x));
}
__device__ __forceinline__ float tanh_hw(float x) {
    float y;
    asm("tanh.approx.f32 %0, %1;" : "=f"(y) : "f"(x));
    return y;
}
__device__ __forceinline__ uint32_t f2tf32(float x) {
    uint32_t r;
    asm("cvt.rna.tf32.f32 %0, %1;" : "=r"(r) : "f"(x));
    return r;
}

__device__ __forceinline__ uint32_t smem_u32(const void* p) {
    return (uint32_t)__cvta_generic_to_shared(p);
}
__device__ __forceinline__ void cp_async16(void* smem, const void* gmem) {
    asm volatile("cp.async.cg.shared.global [%0], [%1], 16;"
                 :: "r"(smem_u32(smem)), "l"(gmem));
}
__device__ __forceinline__ void cp_commit() {
    asm volatile("cp.async.commit_group;");
}
template <int N>
__device__ __forceinline__ void cp_wait() {
    asm volatile("cp.async.wait_group %0;" :: "n"(N));
}

__device__ __forceinline__ void mma_tf32(float* c, const uint32_t* a, const uint32_t* b) {
    asm volatile(
        "mma.sync.aligned.m16n8k8.row.col.f32.tf32.tf32.f32 "
        "{%0,%1,%2,%3},{%4,%5,%6,%7},{%8,%9},{%0,%1,%2,%3};"
        : "+f"(c[0]), "+f"(c[1]), "+f"(c[2]), "+f"(c[3])
        : "r"(a[0]), "r"(a[1]), "r"(a[2]), "r"(a[3]), "r"(b[0]), "r"(b[1]));
}
__device__ __forceinline__ void mma_f16(float* c, const uint32_t* a, const uint32_t* b) {
    asm volatile(
        "mma.sync.aligned.m16n8k16.row.col.f32.f16.f16.f32 "
        "{%0,%1,%2,%3},{%4,%5,%6,%7},{%8,%9},{%0,%1,%2,%3};"
        : "+f"(c[0]), "+f"(c[1]), "+f"(c[2]), "+f"(c[3])
        : "r"(a[0]), "r"(a[1]), "r"(a[2]), "r"(a[3]), "r"(b[0]), "r"(b[1]));
}

// ---------------- TF32 NT GEMM (precompute only: token_gates / token_preds) ----------
template <int BM, int BN, int BK, int WM, int WN, int STAGES>
__global__ void __launch_bounds__((BM / WM) * (BN / WN) * 32, 2)
mma_nt_kernel(int M, int N, int K,
              const float* __restrict__ A, int lda,
              const float* __restrict__ B, int ldb,
              float* __restrict__ C, int ldc,
              const float* __restrict__ bias0) {
    constexpr int WARPS_M = BM / WM, WARPS_N = BN / WN;
    constexpr int NW = WARPS_M * WARPS_N, THREADS = NW * 32;
    constexpr int MI = WM / 16, NI = WN / 8, KI = BK / 8;
    constexpr int LDS_ = BK + 4;
    constexpr int A_CP = BM * (BK / 4) / THREADS;
    constexpr int B_CP = BN * (BK / 4) / THREADS;

    __shared__ __align__(16) float As[STAGES][BM][LDS_];
    __shared__ __align__(16) float Bs[STAGES][BN][LDS_];

    const int tid = threadIdx.x;
    const int wid = tid >> 5, lane = tid & 31;
    const int wm = (wid / WARPS_N) * WM, wn = (wid % WARPS_N) * WN;
    const int g = lane >> 2, tg = lane & 3;
    const int bm = blockIdx.y * BM, bn = blockIdx.x * BN;

    float acc[MI][NI][4];
#pragma unroll
    for (int i = 0; i < MI; i++)
#pragma unroll
        for (int j = 0; j < NI; j++)
#pragma unroll
            for (int q = 0; q < 4; q++) acc[i][j][q] = 0.0f;

    auto issue_tile = [&](int tile, int slot) {
        const int k0 = tile * BK;
#pragma unroll
        for (int i = 0; i < A_CP; i++) {
            int idx = tid + i * THREADS;
            int m = idx / (BK / 4), kq = (idx % (BK / 4)) * 4;
            cp_async16(&As[slot][m][kq], A + (size_t)(bm + m) * lda + k0 + kq);
        }
#pragma unroll
        for (int i = 0; i < B_CP; i++) {
            int idx = tid + i * THREADS;
            int n = idx / (BK / 4), kq = (idx % (BK / 4)) * 4;
            cp_async16(&Bs[slot][n][kq], B + (size_t)(bn + n) * ldb + k0 + kq);
        }
    };

    const int ntiles = K / BK;
#pragma unroll
    for (int s = 0; s < STAGES - 1; s++) {
        issue_tile(s, s);
        cp_commit();
    }

    for (int t = 0; t < ntiles; t++) {
        cp_wait<STAGES - 2>();
        __syncthreads();
        const int slot = t % STAGES;
#pragma unroll
        for (int ki = 0; ki < KI; ki++) {
            const int k_lo = ki * 8 + tg, k_hi = k_lo + 4;
            uint32_t af[MI][4];
            uint32_t bfv[NI][2];
#pragma unroll
            for (int mi = 0; mi < MI; mi++) {
                const int mr = wm + mi * 16 + g;
                af[mi][0] = f2tf32(As[slot][mr][k_lo]);
                af[mi][1] = f2tf32(As[slot][mr + 8][k_lo]);
                af[mi][2] = f2tf32(As[slot][mr][k_hi]);
                af[mi][3] = f2tf32(As[slot][mr + 8][k_hi]);
            }
#pragma unroll
            for (int ni = 0; ni < NI; ni++) {
                const int nr = wn + ni * 8 + g;
                bfv[ni][0] = f2tf32(Bs[slot][nr][k_lo]);
                bfv[ni][1] = f2tf32(Bs[slot][nr][k_hi]);
            }
#pragma unroll
            for (int mi = 0; mi < MI; mi++)
#pragma unroll
                for (int ni = 0; ni < NI; ni++) mma_tf32(acc[mi][ni], af[mi], bfv[ni]);
        }
        if (t + STAGES - 1 < ntiles) issue_tile(t + STAGES - 1, (t + STAGES - 1) % STAGES);
        cp_commit();
    }

#pragma unroll
    for (int mi = 0; mi < MI; mi++) {
#pragma unroll
        for (int ni = 0; ni < NI; ni++) {
            const int col = bn + wn + ni * 8 + tg * 2;
#pragma unroll
            for (int half = 0; half < 2; half++) {
                const int row = bm + wm + mi * 16 + g + half * 8;
                float v0 = acc[mi][ni][half * 2 + 0];
                float v1 = acc[mi][ni][half * 2 + 1];
                if (bias0) { v0 += bias0[col]; v1 += bias0[col + 1]; }
                *(float2*)(C + (size_t)row * ldc + col) = make_float2(v0, v1);
            }
        }
    }
}

// ---------------- FP16 NT GEMM (m16n8k16), full epilogue ----------------
// C = A(MxK,h) * B(NxK,h)^T; out fp32 (+bias0+Cin[rowtok]) or fp16.
template <int BM, int BN, int BK, int WM, int WN, int STAGES>
__global__ void __launch_bounds__((BM / WM) * (BN / WN) * 32, 2)
hgemm_nt_kernel(int M, int N, int K,
                const __half* __restrict__ A, int lda,
                const __half* __restrict__ B, int ldb,
                void* __restrict__ Cv, int ldc,
                const float* __restrict__ Cin, int ldcin,
                const float* __restrict__ bias0,
                const int* __restrict__ rowtok, int rts,
                int out_f16) {
    constexpr int WARPS_M = BM / WM, WARPS_N = BN / WN;
    constexpr int NW = WARPS_M * WARPS_N, THREADS = NW * 32;
    constexpr int MI = WM / 16, NI = WN / 8, KI = BK / 16;
    constexpr int LDS_ = BK + 8;  // halves; 80B row stride -> conflict-free frags
    constexpr int A_CP = BM * (BK / 8) / THREADS;
    constexpr int B_CP = BN * (BK / 8) / THREADS;

    __shared__ __align__(16) __half As[STAGES][BM][LDS_];
    __shared__ __align__(16) __half Bs[STAGES][BN][LDS_];

    const int tid = threadIdx.x;
    const int wid = tid >> 5, lane = tid & 31;
    const int wm = (wid / WARPS_N) * WM, wn = (wid % WARPS_N) * WN;
    const int g = lane >> 2, tg = lane & 3;
    const int bm = blockIdx.y * BM, bn = blockIdx.x * BN;

    float acc[MI][NI][4];
#pragma unroll
    for (int i = 0; i < MI; i++)
#pragma unroll
        for (int j = 0; j < NI; j++)
#pragma unroll
            for (int q = 0; q < 4; q++) acc[i][j][q] = 0.0f;

    auto issue_tile = [&](int tile, int slot) {
        const int k0 = tile * BK;
#pragma unroll
        for (int i = 0; i < A_CP; i++) {
            int idx = tid + i * THREADS;
            int m = idx / (BK / 8), kq = (idx % (BK / 8)) * 8;
            cp_async16(&As[slot][m][kq], A + (size_t)(bm + m) * lda + k0 + kq);
        }
#pragma unroll
        for (int i = 0; i < B_CP; i++) {
            int idx = tid + i * THREADS;
            int n = idx / (BK / 8), kq = (idx % (BK / 8)) * 8;
            cp_async16(&Bs[slot][n][kq], B + (size_t)(bn + n) * ldb + k0 + kq);
        }
    };

    const int ntiles = K / BK;
#pragma unroll
    for (int s = 0; s < STAGES - 1; s++) {
        issue_tile(s, s);
        cp_commit();
    }

    for (int t = 0; t < ntiles; t++) {
        cp_wait<STAGES - 2>();
        __syncthreads();
        const int slot = t % STAGES;

#pragma unroll
        for (int ki = 0; ki < KI; ki++) {
            const int kb = ki * 16 + tg * 2;
            uint32_t af[MI][4];
            uint32_t bfv[NI][2];
#pragma unroll
            for (int mi = 0; mi < MI; mi++) {
                const int mr = wm + mi * 16 + g;
                af[mi][0] = *(const uint32_t*)&As[slot][mr][kb];
                af[mi][1] = *(const uint32_t*)&As[slot][mr + 8][kb];
                af[mi][2] = *(const uint32_t*)&As[slot][mr][kb + 8];
                af[mi][3] = *(const uint32_t*)&As[slot][mr + 8][kb + 8];
            }
#pragma unroll
            for (int ni = 0; ni < NI; ni++) {
                const int nr = wn + ni * 8 + g;
                bfv[ni][0] = *(const uint32_t*)&Bs[slot][nr][kb];
                bfv[ni][1] = *(const uint32_t*)&Bs[slot][nr][kb + 8];
            }
#pragma unroll
            for (int mi = 0; mi < MI; mi++)
#pragma unroll
                for (int ni = 0; ni < NI; ni++) mma_f16(acc[mi][ni], af[mi], bfv[ni]);
        }

        if (t + STAGES - 1 < ntiles) issue_tile(t + STAGES - 1, (t + STAGES - 1) % STAGES);
        cp_commit();
    }

#pragma unroll
    for (int mi = 0; mi < MI; mi++) {
#pragma unroll
        for (int ni = 0; ni < NI; ni++) {
            const int col = bn + wn + ni * 8 + tg * 2;
#pragma unroll
            for (int half = 0; half < 2; half++) {
                const int row = bm + wm + mi * 16 + g + half * 8;
                float v0 = acc[mi][ni][half * 2 + 0];
                float v1 = acc[mi][ni][half * 2 + 1];
                if (out_f16) {
                    __half2* cp = (__half2*)((__half*)Cv + (size_t)row * ldc + col);
                    *cp = __floats2half2_rn(v0, v1);
                    continue;
                }
                float* C = (float*)Cv;
                if (bias0) { v0 += bias0[col]; v1 += bias0[col + 1]; }
                if (Cin) {
                    const int crow = rowtok ? rowtok[row * rts] : row;
                    float2 ci = *(const float2*)(Cin + (size_t)crow * ldcin + col);
                    v0 += ci.x; v1 += ci.y;
                }
                *(float2*)(C + (size_t)row * ldc + col) = make_float2(v0, v1);
            }
        }
    }
}

template <int BM, int BN, int BK, int WM, int WN, int STAGES>
static void hgemm(int M, int N, int K,
                  const __half* A, int lda, const __half* B, int ldb,
                  void* C, int ldc,
                  const float* Cin = nullptr, int ldcin = 0,
                  const float* bias0 = nullptr,
                  const int* rowtok = nullptr, int rts = 1,
                  bool out_f16 = false) {
    dim3 grid(N / BN, M / BM);
    hgemm_nt_kernel<BM, BN, BK, WM, WN, STAGES>
        <<<grid, (BM / WM) * (BN / WN) * 32>>>(
            M, N, K, A, lda, B, ldb, C, ldc, Cin, ldcin, bias0, rowtok, rts,
            out_f16 ? 1 : 0);
}

// ---------------- precompute kernels ----------------
__global__ void tokens_kernel(const int* __restrict__ targets, int* __restrict__ toks) {
    int idx = blockIdx.x * blockDim.x + threadIdx.x;  // B*T
    int t = idx & (TT - 1);
    int b = idx >> 5;
    toks[idx] = (t == 0) ? EOS_IDX : targets[b * TT + t - 1];
}

// combined weights -> fp16; also pre-summed biases
__global__ void build_wcomb_kernel(const float* __restrict__ W_ih0,
                                   const float* __restrict__ W_hh0,
                                   const float* __restrict__ W_ih1,
                                   const float* __restrict__ W_hh1,
                                   const float* __restrict__ b_ih0,
                                   const float* __restrict__ b_hh0,
                                   const float* __restrict__ b_ih1,
                                   const float* __restrict__ b_hh1,
                                   __half* __restrict__ Wc0,
                                   __half* __restrict__ Wc1,
                                   float* __restrict__ bsum0,
                                   float* __restrict__ bsum1) {
    int idx = blockIdx.x * blockDim.x + threadIdx.x;
    const int N0 = G4H * (DENC + HH);
    const int N1 = G4H * (HH + HH);
    if (idx < N0) {
        int n = idx / (DENC + HH);
        int k = idx % (DENC + HH);
        float v = (k < DENC) ? W_ih0[(size_t)n * (EE + DENC) + EE + k]
                             : W_hh0[(size_t)n * HH + (k - DENC)];
        Wc0[idx] = __float2half_rn(v);
    } else if (idx < N0 + N1) {
        int r = idx - N0;
        int n = r / (HH + HH);
        int k = r % (HH + HH);
        float v = (k < HH) ? W_ih1[(size_t)n * HH + k]
                           : W_hh1[(size_t)n * HH + (k - HH)];
        Wc1[r] = __float2half_rn(v);
    } else if (idx < N0 + N1 + G4H) {
        int r = idx - N0 - N1;
        bsum0[r] = b_ih0[r] + b_hh0[r];
    } else if (idx < N0 + N1 + 2 * G4H) {
        int r = idx - N0 - N1 - G4H;
        bsum1[r] = b_ih1[r] + b_hh1[r];
    }
}

// fp16 copies of W_dec, W_enc, compact W_out[:, :PCOL]
__global__ void round_weights_kernel(const float* __restrict__ W_dec,
                                     const float* __restrict__ W_enc,
                                     const float* __restrict__ W_out,
                                     __half* __restrict__ Wdec_h,
                                     __half* __restrict__ Wenc_h,
                                     __half* __restrict__ Wout_h) {
    int idx = blockIdx.x * blockDim.x + threadIdx.x;
    const int N0 = HH * HH;
    const int N1 = HH * DENC;
    const int N2 = VV * PCOL;
    if (idx < N0) {
        Wdec_h[idx] = __float2half_rn(W_dec[idx]);
    } else if (idx < N0 + N1) {
        int r = idx - N0;
        Wenc_h[r] = __float2half_rn(W_enc[r]);
    } else if (idx < N0 + N1 + N2) {
        int r = idx - N0 - N1;
        int row = r / PCOL, col = r % PCOL;
        Wout_h[r] = __float2half_rn(W_out[(size_t)row * (HH + DENC + EE) + col]);
    }
}

// fp32 -> fp16 bulk convert (4 elems/thread)
__global__ void cvt_f16_kernel(const float* __restrict__ in,
                               __half* __restrict__ out, int n4) {
    int i = blockIdx.x * blockDim.x + threadIdx.x;
    if (i < n4) {
        float4 v = ((const float4*)in)[i];
        ((__half2*)out)[2 * i] = __floats2half2_rn(v.x, v.y);
        ((__half2*)out)[2 * i + 1] = __floats2half2_rn(v.z, v.w);
    }
}

__global__ void init_state_kernel(const float* __restrict__ h0,
                                  const float* __restrict__ c0,
                                  __half* __restrict__ xbuf,
                                  __half* __restrict__ x1buf,
                                  float* __restrict__ cb0,
                                  float* __restrict__ cb1) {
    int idx = blockIdx.x * blockDim.x + threadIdx.x;  // B*H
    int b = idx >> 9;
    int h = idx & (HH - 1);
    xbuf[(size_t)b * (DENC + HH) + DENC + h] = __float2half_rn(h0[idx]);
    x1buf[(size_t)b * (HH + HH) + HH + h] = __float2half_rn(h0[(size_t)BB * HH + idx]);
    cb0[idx] = c0[idx];
    cb1[idx] = c0[(size_t)BB * HH + idx];
}

// ---------------- attention (fused score/tanh + masked softmax + context) ----------------
__global__ void __launch_bounds__(256) attention_kernel(
    const __half* __restrict__ enc_proj,   // (B,S,H) fp16
    const __half* __restrict__ enc,        // (B,S,DENC) fp16
    const float* __restrict__ decp,        // (B,H)
    const float* __restrict__ vvec,        // (H)
    const int* __restrict__ mask,          // (B,S)
    __half* __restrict__ ctx_dst1, int ld1,
    __half* __restrict__ ctx_dst2, int ld2) {
    const int b = blockIdx.x;
    __shared__ float s_dp[HH];
    __shared__ float s_v[HH];
    __shared__ float s_w[SS];
    __shared__ float s_red[2];
    const int tid = threadIdx.x;
    const int warp = tid >> 5, lane = tid & 31;

    for (int i = tid; i < HH; i += 256) {
        s_dp[i] = decp[(size_t)b * HH + i];
        s_v[i] = vvec[i];
    }
    __syncthreads();

    for (int s = warp; s < SS; s += 8) {
        const uint2* ep = (const uint2*)(enc_proj + ((size_t)b * SS + s) * HH);
        float acc = 0.0f;
#pragma unroll
        for (int h4 = lane; h4 < HH / 4; h4 += 32) {
            uint2 raw = ep[h4];
            float2 e01 = __half22float2(*(const __half2*)&raw.x);
            float2 e23 = __half22float2(*(const __half2*)&raw.y);
            float4 sv = *(const float4*)&s_v[4 * h4];
            float4 sd = *(const float4*)&s_dp[4 * h4];
            acc += sv.x * tanh_hw(sd.x + e01.x);
            acc += sv.y * tanh_hw(sd.y + e01.y);
            acc += sv.z * tanh_hw(sd.z + e23.x);
            acc += sv.w * tanh_hw(sd.w + e23.y);
        }
#pragma unroll
        for (int o = 16; o; o >>= 1) acc += __shfl_xor_sync(0xffffffffu, acc, o);
        if (lane == 0) s_w[s] = mask[b * SS + s] ? acc : -1e30f;
    }
    __syncthreads();

    if (warp == 0) {
        float m = fmaxf(s_w[lane], s_w[lane + 32]);
#pragma unroll
        for (int o = 16; o; o >>= 1) m = fmaxf(m, __shfl_xor_sync(0xffffffffu, m, o));
        float sum = __expf(s_w[lane] - m) + __expf(s_w[lane + 32] - m);
#pragma unroll
        for (int o = 16; o; o >>= 1) sum += __shfl_xor_sync(0xffffffffu, sum, o);
        if (lane == 0) { s_red[0] = m; s_red[1] = sum; }
    }
    __syncthreads();
    const float m = s_red[0], inv = 1.0f / s_red[1];
    if (tid < SS) s_w[tid] = __expf(s_w[tid] - m) * inv;
    __syncthreads();

    // context: thread tid owns 4 d-elems; fp32 accum, fp16 store
    const __half2* eb2 = (const __half2*)(enc + (size_t)b * SS * DENC);
    float4 acc4 = make_float4(0.f, 0.f, 0.f, 0.f);
#pragma unroll 8
    for (int s = 0; s < SS; s++) {
        const float w = s_w[s];
        uint2 raw = *(const uint2*)(eb2 + (size_t)s * (DENC / 2) + 2 * tid);
        float2 e01 = __half22float2(*(const __half2*)&raw.x);
        float2 e23 = __half22float2(*(const __half2*)&raw.y);
        acc4.x += w * e01.x; acc4.y += w * e01.y;
        acc4.z += w * e23.x; acc4.w += w * e23.y;
    }
    __half2 c01 = __floats2half2_rn(acc4.x, acc4.y);
    __half2 c23 = __floats2half2_rn(acc4.z, acc4.w);
    *(__half2*)(ctx_dst1 + (size_t)b * ld1 + 4 * tid) = c01;
    *(__half2*)(ctx_dst1 + (size_t)b * ld1 + 4 * tid + 2) = c23;
    *(__half2*)(ctx_dst2 + (size_t)b * ld2 + 4 * tid) = c01;
    *(__half2*)(ctx_dst2 + (size_t)b * ld2 + 4 * tid + 2) = c23;
}

// ---------------- LSTM pointwise cell (vectorized; fp16 h stores) ----------------
__global__ void lstm_cell_kernel(const float* __restrict__ gates,  // (B,4H)
                                 float* __restrict__ c,            // (B,H) in/out
                                 __half* __restrict__ hA, int ldA,
                                 __half* __restrict__ hB, int ldB) {
    int idx = blockIdx.x * blockDim.x + threadIdx.x;  // B*H/4
    int b = idx / (HH / 4);
    int q = idx % (HH / 4);
    const float* gp = gates + (size_t)b * G4H + 4 * q;
    float4 gi = *(const float4*)(gp);
    float4 gf = *(const float4*)(gp + HH);
    float4 gg = *(const float4*)(gp + 2 * HH);
    float4 go = *(const float4*)(gp + 3 * HH);
    float4 cc = *(float4*)(c + (size_t)b * HH + 4 * q);
    float4 cn;
    cn.x = sigmoid_fast(gf.x) * cc.x + sigmoid_fast(gi.x) * tanhf(gg.x);
    cn.y = sigmoid_fast(gf.y) * cc.y + sigmoid_fast(gi.y) * tanhf(gg.y);
    cn.z = sigmoid_fast(gf.z) * cc.z + sigmoid_fast(gi.z) * tanhf(gg.z);
    cn.w = sigmoid_fast(gf.w) * cc.w + sigmoid_fast(gi.w) * tanhf(gg.w);
    __half2 h01 = __floats2half2_rn(sigmoid_fast(go.x) * tanhf(cn.x),
                                    sigmoid_fast(go.y) * tanhf(cn.y));
    __half2 h23 = __floats2half2_rn(sigmoid_fast(go.z) * tanhf(cn.z),
                                    sigmoid_fast(go.w) * tanhf(cn.w));
    *(float4*)(c + (size_t)b * HH + 4 * q) = cn;
    *(__half2*)(hA + (size_t)b * ldA + 4 * q) = h01;
    *(__half2*)(hA + (size_t)b * ldA + 4 * q + 2) = h23;
    *(__half2*)(hB + (size_t)b * ldB + 4 * q) = h01;
    *(__half2*)(hB + (size_t)b * ldB + 4 * q + 2) = h23;
}

// ---------------- host ----------------
extern "C" void kernel_launch(void* const* d_in, const int* in_sizes, int n_in,
                              void* d_out, int out_size) {
    const float* encoder_out = (const float*)d_in[0];
    const float* h0   = (const float*)d_in[1];
    const float* c0   = (const float*)d_in[2];
    const int*   targets = (const int*)d_in[3];
    const int*   mask    = (const int*)d_in[4];
    const float* emb   = (const float*)d_in[5];
    const float* W_enc = (const float*)d_in[6];
    const float* W_dec = (const float*)d_in[7];
    const float* vvec  = (const float*)d_in[8];
    const float* W_ih0 = (const float*)d_in[9];
    const float* W_hh0 = (const float*)d_in[10];
    const float* b_ih0 = (const float*)d_in[11];
    const float* b_hh0 = (const float*)d_in[12];
    const float* W_ih1 = (const float*)d_in[13];
    const float* W_hh1 = (const float*)d_in[14];
    const float* b_ih1 = (const float*)d_in[15];
    const float* b_hh1 = (const float*)d_in[16];
    const float* W_out = (const float*)d_in[17];
    const float* b_out = (const float*)d_in[18];
    float* out = (float*)d_out;  // (B,T,V)

    __half *p_encproj_h, *p_enc_h, *p_Wenc_h, *p_pred, *p_Wc0, *p_Wc1, *p_Wdec, *p_Wout;
    __half *p_xbuf, *p_x1buf;
    float *p_tokg, *p_tokp, *p_bsum0, *p_bsum1, *p_gates, *p_c0, *p_c1, *p_decproj;
    int* p_tokens;
    cudaGetSymbolAddress((void**)&p_encproj_h, g_encproj_h);
    cudaGetSymbolAddress((void**)&p_enc_h, g_enc_h);
    cudaGetSymbolAddress((void**)&p_Wenc_h, g_Wenc_h);
    cudaGetSymbolAddress((void**)&p_pred, g_pred);
    cudaGetSymbolAddress((void**)&p_Wc0, g_Wc0);
    cudaGetSymbolAddress((void**)&p_Wc1, g_Wc1);
    cudaGetSymbolAddress((void**)&p_Wdec, g_Wdec_h);
    cudaGetSymbolAddress((void**)&p_Wout, g_Wout_h);
    cudaGetSymbolAddress((void**)&p_tokg, g_token_gates);
    cudaGetSymbolAddress((void**)&p_tokp, g_token_preds);
    cudaGetSymbolAddress((void**)&p_bsum0, g_bsum0);
    cudaGetSymbolAddress((void**)&p_bsum1, g_bsum1);
    cudaGetSymbolAddress((void**)&p_tokens, g_tokens);
    cudaGetSymbolAddress((void**)&p_xbuf, g_xbuf);
    cudaGetSymbolAddress((void**)&p_x1buf, g_x1buf);
    cudaGetSymbolAddress((void**)&p_gates, g_gates);
    cudaGetSymbolAddress((void**)&p_c0, g_c0buf);
    cudaGetSymbolAddress((void**)&p_c1, g_c1buf);
    cudaGetSymbolAddress((void**)&p_decproj, g_decproj);

    // ---- precompute ----
    tokens_kernel<<<(BB * TT) / 256, 256>>>(targets, p_tokens);
    {
        int total = G4H * (DENC + HH) + G4H * (HH + HH) + 2 * G4H;
        build_wcomb_kernel<<<(total + 255) / 256, 256>>>(
            W_ih0, W_hh0, W_ih1, W_hh1, b_ih0, b_hh0, b_ih1, b_hh1,
            p_Wc0, p_Wc1, p_bsum0, p_bsum1);
    }
    {
        int total = HH * HH + HH * DENC + VV * PCOL;
        round_weights_kernel<<<(total + 255) / 256, 256>>>(W_dec, W_enc, W_out,
                                                           p_Wdec, p_Wenc_h, p_Wout);
    }
    {
        int n4 = (BB * SS * DENC) / 4;
        cvt_f16_kernel<<<(n4 + 255) / 256, 256>>>(encoder_out, p_enc_h, n4);
    }
    init_state_kernel<<<(BB * HH) / 256, 256>>>(h0, c0, p_xbuf, p_x1buf, p_c0, p_c1);

    // token_gates (V,4H) = emb @ W_ih0[:, :E]^T  (tf32 path, raw fp32 operands)
    {
        dim3 grid(G4H / 128, VV / 64);
        mma_nt_kernel<64, 128, 16, 32, 64, 4><<<grid, 128>>>(
            VV, G4H, EE, emb, EE, W_ih0, EE + DENC, p_tokg, G4H, nullptr);
    }
    // token_preds (V,V) = emb @ W_out[:, H+DENC:]^T + b_out
    {
        dim3 grid(VV / 64, VV / 64);
        mma_nt_kernel<64, 64, 16, 32, 32, 4><<<grid, 128>>>(
            VV, VV, EE, emb, EE, W_out + (HH + DENC), HH + DENC + EE, p_tokp, VV, b_out);
    }
    // enc_proj -> fp16 (score path)
    hgemm<128, 128, 32, 64, 32, 3>(BB * SS, HH, DENC, p_enc_h, DENC, p_Wenc_h, DENC,
                                   p_encproj_h, HH, nullptr, 0, nullptr,
                                   nullptr, 1, true);

    // ---- sequential decode ----
    for (int t = 0; t < TT; t++) {
        // dec_proj = h1 @ Wdec^T  (fp16)
        hgemm<64, 64, 32, 32, 32, 4>(BB, HH, HH, p_x1buf + HH, HH + HH, p_Wdec, HH,
                                     p_decproj, HH);

        // attention: context -> xbuf[:, :DENC] and pred[:, t, H:]
        attention_kernel<<<BB, 256>>>(p_encproj_h, p_enc_h, p_decproj, vvec, mask,
                                      p_xbuf, DENC + HH,
                                      p_pred + (size_t)t * PCOL + HH, TT * PCOL);

        // gates0 = [context|h0] @ Wc0^T + token_gates[tok(b,t)] + bsum0  (grid 256)
        hgemm<64, 64, 32, 32, 32, 4>(BB, G4H, DENC + HH, p_xbuf, DENC + HH,
                                     p_Wc0, DENC + HH, p_gates, G4H,
                                     p_tokg, G4H, p_bsum0,
                                     p_tokens + t, TT);
        lstm_cell_kernel<<<(BB * HH / 4) / 256, 256>>>(p_gates, p_c0,
                                                       p_x1buf, HH + HH,
                                                       p_xbuf + DENC, DENC + HH);

        // gates1 = [h0n|h1] @ Wc1^T + bsum1  (grid 256)
        hgemm<64, 64, 32, 32, 32, 4>(BB, G4H, HH + HH, p_x1buf, HH + HH,
                                     p_Wc1, HH + HH, p_gates, G4H,
                                     nullptr, 0, p_bsum1);
        lstm_cell_kernel<<<(BB * HH / 4) / 256, 256>>>(p_gates, p_c1,
                                                       p_x1buf + HH, HH + HH,
                                                       p_pred + (size_t)t * PCOL, TT * PCOL);
    }

    // logits: out = [h1n|context] @ Wout^T + token_preds[tok(b,t)]
    hgemm<64, 128, 32, 32, 64, 4>(BB * TT, VV, PCOL, p_pred, PCOL, p_Wout, PCOL,
                                  out, VV, p_tokp, VV, nullptr,
                                  p_tokens, 1);
}

// round 16
// speedup vs baseline: 1.8428x; 1.0258x over previous
#include <cuda_runtime.h>
#include <cuda_fp16.h>
#include <math.h>
#include <stdint.h>

#define BB 512
#define SS 64
#define TT 32
#define VV 128
#define EE 256
#define HH 512
#define DENC 1024
#define G4H 2048
#define EOS_IDX 2
#define PCOL (HH + DENC)  /* 1536 */

// ---------------- scratch (device globals; no allocations) ----------------
__device__ __half g_encproj_h[(size_t)BB * SS * HH];   // 32 MB (score path)
__device__ __half g_enc_h[(size_t)BB * SS * DENC];     // 64 MB (attention + enc_proj A)
__device__ __half g_Wenc_h[HH * DENC];
__device__ __half g_pred[(size_t)BB * TT * PCOL];      // 50 MB [h1n | context] fp16
__device__ __half g_Wc0[G4H * (DENC + HH)];            // fp16 [W_ih0[:,E:] | W_hh0]
__device__ __half g_Wc1[G4H * (HH + HH)];              // fp16 [W_ih1 | W_hh1]
__device__ __half g_Wdec_h[HH * HH];
__device__ __half g_Wout_h[VV * PCOL];                 // compact W_out[:, :PCOL]
__device__ float g_token_gates[VV * G4H];              // per-token gates add (fp32 Cin)
__device__ float g_token_preds[VV * VV];               // per-token logits add (fp32 Cin)
__device__ float g_bsum0[G4H];                         // b_ih0 + b_hh0
__device__ float g_bsum1[G4H];                         // b_ih1 + b_hh1
__device__ int   g_tokens[BB * TT];
__device__ __half g_xbuf[BB * (DENC + HH)];            // [context | h0] fp16
__device__ __half g_x1buf[BB * (HH + HH)];             // [h0n | h1] fp16
__device__ __half g_gates[BB * G4H];                   // fp16 gate pre-activations
__device__ float g_c0buf[BB * HH];
__device__ float g_c1buf[BB * HH];
__device__ float g_decproj[BB * HH];

__device__ __forceinline__ float sigmoid_fast(float x) {
    return __fdividef(1.0f, 1.0f + __expf(-x));
}
// tanh via __expf: ~1e-6 abs err (clamp avoids inf through __fdividef)
__device__ __forceinline__ float tanh_fast(float x) {
    float xc = fminf(fmaxf(x, -10.0f), 10.0f);
    return 1.0f - __fdividef(2.0f, __expf(2.0f * xc) + 1.0f);
}
__device__ __forceinline__ float tanh_hw(float x) {
    float y;
    asm("tanh.approx.f32 %0, %1;" : "=f"(y) : "f"(x));
    return y;
}
__device__ __forceinline__ uint32_t f2tf32(float x) {
    uint32_t r;
    asm("cvt.rna.tf32.f32 %0, %1;" : "=r"(r) : "f"(x));
    return r;
}

__device__ __forceinline__ uint32_t smem_u32(const void* p) {
    return (uint32_t)__cvta_generic_to_shared(p);
}
__device__ __forceinline__ void cp_async16(void* smem, const void* gmem) {
    asm volatile("cp.async.cg.shared.global [%0], [%1], 16;"
                 :: "r"(smem_u32(smem)), "l"(gmem));
}
__device__ __forceinline__ void cp_commit() {
    asm volatile("cp.async.commit_group;");
}
template <int N>
__device__ __forceinline__ void cp_wait() {
    asm volatile("cp.async.wait_group %0;" :: "n"(N));
}

__device__ __forceinline__ void mma_tf32(float* c, const uint32_t* a, const uint32_t* b) {
    asm volatile(
        "mma.sync.aligned.m16n8k8.row.col.f32.tf32.tf32.f32 "
        "{%0,%1,%2,%3},{%4,%5,%6,%7},{%8,%9},{%0,%1,%2,%3};"
        : "+f"(c[0]), "+f"(c[1]), "+f"(c[2]), "+f"(c[3])
        : "r"(a[0]), "r"(a[1]), "r"(a[2]), "r"(a[3]), "r"(b[0]), "r"(b[1]));
}
__device__ __forceinline__ void mma_f16(float* c, const uint32_t* a, const uint32_t* b) {
    asm volatile(
        "mma.sync.aligned.m16n8k16.row.col.f32.f16.f16.f32 "
        "{%0,%1,%2,%3},{%4,%5,%6,%7},{%8,%9},{%0,%1,%2,%3};"
        : "+f"(c[0]), "+f"(c[1]), "+f"(c[2]), "+f"(c[3])
        : "r"(a[0]), "r"(a[1]), "r"(a[2]), "r"(a[3]), "r"(b[0]), "r"(b[1]));
}

// ---------------- TF32 NT GEMM (precompute only: token_gates / token_preds) ----------
template <int BM, int BN, int BK, int WM, int WN, int STAGES>
__global__ void __launch_bounds__((BM / WM) * (BN / WN) * 32, 2)
mma_nt_kernel(int M, int N, int K,
              const float* __restrict__ A, int lda,
              const float* __restrict__ B, int ldb,
              float* __restrict__ C, int ldc,
              const float* __restrict__ bias0) {
    constexpr int WARPS_M = BM / WM, WARPS_N = BN / WN;
    constexpr int NW = WARPS_M * WARPS_N, THREADS = NW * 32;
    constexpr int MI = WM / 16, NI = WN / 8, KI = BK / 8;
    constexpr int LDS_ = BK + 4;
    constexpr int A_CP = BM * (BK / 4) / THREADS;
    constexpr int B_CP = BN * (BK / 4) / THREADS;

    __shared__ __align__(16) float As[STAGES][BM][LDS_];
    __shared__ __align__(16) float Bs[STAGES][BN][LDS_];

    const int tid = threadIdx.x;
    const int wid = tid >> 5, lane = tid & 31;
    const int wm = (wid / WARPS_N) * WM, wn = (wid % WARPS_N) * WN;
    const int g = lane >> 2, tg = lane & 3;
    const int bm = blockIdx.y * BM, bn = blockIdx.x * BN;

    float acc[MI][NI][4];
#pragma unroll
    for (int i = 0; i < MI; i++)
#pragma unroll
        for (int j = 0; j < NI; j++)
#pragma unroll
            for (int q = 0; q < 4; q++) acc[i][j][q] = 0.0f;

    auto issue_tile = [&](int tile, int slot) {
        const int k0 = tile * BK;
#pragma unroll
        for (int i = 0; i < A_CP; i++) {
            int idx = tid + i * THREADS;
            int m = idx / (BK / 4), kq = (idx % (BK / 4)) * 4;
            cp_async16(&As[slot][m][kq], A + (size_t)(bm + m) * lda + k0 + kq);
        }
#pragma unroll
        for (int i = 0; i < B_CP; i++) {
            int idx = tid + i * THREADS;
            int n = idx / (BK / 4), kq = (idx % (BK / 4)) * 4;
            cp_async16(&Bs[slot][n][kq], B + (size_t)(bn + n) * ldb + k0 + kq);
        }
    };

    const int ntiles = K / BK;
#pragma unroll
    for (int s = 0; s < STAGES - 1; s++) {
        issue_tile(s, s);
        cp_commit();
    }

    for (int t = 0; t < ntiles; t++) {
        cp_wait<STAGES - 2>();
        __syncthreads();
        const int slot = t % STAGES;
#pragma unroll
        for (int ki = 0; ki < KI; ki++) {
            const int k_lo = ki * 8 + tg, k_hi = k_lo + 4;
            uint32_t af[MI][4];
            uint32_t bfv[NI][2];
#pragma unroll
            for (int mi = 0; mi < MI; mi++) {
                const int mr = wm + mi * 16 + g;
                af[mi][0] = f2tf32(As[slot][mr][k_lo]);
                af[mi][1] = f2tf32(As[slot][mr + 8][k_lo]);
                af[mi][2] = f2tf32(As[slot][mr][k_hi]);
                af[mi][3] = f2tf32(As[slot][mr + 8][k_hi]);
            }
#pragma unroll
            for (int ni = 0; ni < NI; ni++) {
                const int nr = wn + ni * 8 + g;
                bfv[ni][0] = f2tf32(Bs[slot][nr][k_lo]);
                bfv[ni][1] = f2tf32(Bs[slot][nr][k_hi]);
            }
#pragma unroll
            for (int mi = 0; mi < MI; mi++)
#pragma unroll
                for (int ni = 0; ni < NI; ni++) mma_tf32(acc[mi][ni], af[mi], bfv[ni]);
        }
        if (t + STAGES - 1 < ntiles) issue_tile(t + STAGES - 1, (t + STAGES - 1) % STAGES);
        cp_commit();
    }

#pragma unroll
    for (int mi = 0; mi < MI; mi++) {
#pragma unroll
        for (int ni = 0; ni < NI; ni++) {
            const int col = bn + wn + ni * 8 + tg * 2;
#pragma unroll
            for (int half = 0; half < 2; half++) {
                const int row = bm + wm + mi * 16 + g + half * 8;
                float v0 = acc[mi][ni][half * 2 + 0];
                float v1 = acc[mi][ni][half * 2 + 1];
                if (bias0) { v0 += bias0[col]; v1 += bias0[col + 1]; }
                *(float2*)(C + (size_t)row * ldc + col) = make_float2(v0, v1);
            }
        }
    }
}

// ---------------- FP16 NT GEMM (m16n8k16), full epilogue ----------------
// C = A(MxK,h) * B(NxK,h)^T; epilogue adds bias0 + Cin[rowtok], stores fp32 or fp16.
template <int BM, int BN, int BK, int WM, int WN, int STAGES>
__global__ void __launch_bounds__((BM / WM) * (BN / WN) * 32, 2)
hgemm_nt_kernel(int M, int N, int K,
                const __half* __restrict__ A, int lda,
                const __half* __restrict__ B, int ldb,
                void* __restrict__ Cv, int ldc,
                const float* __restrict__ Cin, int ldcin,
                const float* __restrict__ bias0,
                const int* __restrict__ rowtok, int rts,
                int out_f16) {
    constexpr int WARPS_M = BM / WM, WARPS_N = BN / WN;
    constexpr int NW = WARPS_M * WARPS_N, THREADS = NW * 32;
    constexpr int MI = WM / 16, NI = WN / 8, KI = BK / 16;
    constexpr int LDS_ = BK + 8;  // halves; 80B row stride -> conflict-free frags
    constexpr int A_CP = BM * (BK / 8) / THREADS;
    constexpr int B_CP = BN * (BK / 8) / THREADS;

    __shared__ __align__(16) __half As[STAGES][BM][LDS_];
    __shared__ __align__(16) __half Bs[STAGES][BN][LDS_];

    const int tid = threadIdx.x;
    const int wid = tid >> 5, lane = tid & 31;
    const int wm = (wid / WARPS_N) * WM, wn = (wid % WARPS_N) * WN;
    const int g = lane >> 2, tg = lane & 3;
    const int bm = blockIdx.y * BM, bn = blockIdx.x * BN;

    float acc[MI][NI][4];
#pragma unroll
    for (int i = 0; i < MI; i++)
#pragma unroll
        for (int j = 0; j < NI; j++)
#pragma unroll
            for (int q = 0; q < 4; q++) acc[i][j][q] = 0.0f;

    auto issue_tile = [&](int tile, int slot) {
        const int k0 = tile * BK;
#pragma unroll
        for (int i = 0; i < A_CP; i++) {
            int idx = tid + i * THREADS;
            int m = idx / (BK / 8), kq = (idx % (BK / 8)) * 8;
            cp_async16(&As[slot][m][kq], A + (size_t)(bm + m) * lda + k0 + kq);
        }
#pragma unroll
        for (int i = 0; i < B_CP; i++) {
            int idx = tid + i * THREADS;
            int n = idx / (BK / 8), kq = (idx % (BK / 8)) * 8;
            cp_async16(&Bs[slot][n][kq], B + (size_t)(bn + n) * ldb + k0 + kq);
        }
    };

    const int ntiles = K / BK;
#pragma unroll
    for (int s = 0; s < STAGES - 1; s++) {
        issue_tile(s, s);
        cp_commit();
    }

    for (int t = 0; t < ntiles; t++) {
        cp_wait<STAGES - 2>();
        __syncthreads();
        const int slot = t % STAGES;

#pragma unroll
        for (int ki = 0; ki < KI; ki++) {
            const int kb = ki * 16 + tg * 2;
            uint32_t af[MI][4];
            uint32_t bfv[NI][2];
#pragma unroll
            for (int mi = 0; mi < MI; mi++) {
                const int mr = wm + mi * 16 + g;
                af[mi][0] = *(const uint32_t*)&As[slot][mr][kb];
                af[mi][1] = *(const uint32_t*)&As[slot][mr + 8][kb];
                af[mi][2] = *(const uint32_t*)&As[slot][mr][kb + 8];
                af[mi][3] = *(const uint32_t*)&As[slot][mr + 8][kb + 8];
            }
#pragma unroll
            for (int ni = 0; ni < NI; ni++) {
                const int nr = wn + ni * 8 + g;
                bfv[ni][0] = *(const uint32_t*)&Bs[slot][nr][kb];
                bfv[ni][1] = *(const uint32_t*)&Bs[slot][nr][kb + 8];
            }
#pragma unroll
            for (int mi = 0; mi < MI; mi++)
#pragma unroll
                for (int ni = 0; ni < NI; ni++) mma_f16(acc[mi][ni], af[mi], bfv[ni]);
        }

        if (t + STAGES - 1 < ntiles) issue_tile(t + STAGES - 1, (t + STAGES - 1) % STAGES);
        cp_commit();
    }

#pragma unroll
    for (int mi = 0; mi < MI; mi++) {
#pragma unroll
        for (int ni = 0; ni < NI; ni++) {
            const int col = bn + wn + ni * 8 + tg * 2;
#pragma unroll
            for (int half = 0; half < 2; half++) {
                const int row = bm + wm + mi * 16 + g + half * 8;
                float v0 = acc[mi][ni][half * 2 + 0];
                float v1 = acc[mi][ni][half * 2 + 1];
                if (bias0) { v0 += bias0[col]; v1 += bias0[col + 1]; }
                if (Cin) {
                    const int crow = rowtok ? rowtok[row * rts] : row;
                    float2 ci = *(const float2*)(Cin + (size_t)crow * ldcin + col);
                    v0 += ci.x; v1 += ci.y;
                }
                if (out_f16) {
                    __half2* cp = (__half2*)((__half*)Cv + (size_t)row * ldc + col);
                    *cp = __floats2half2_rn(v0, v1);
                } else {
                    float* C = (float*)Cv;
                    *(float2*)(C + (size_t)row * ldc + col) = make_float2(v0, v1);
                }
            }
        }
    }
}

template <int BM, int BN, int BK, int WM, int WN, int STAGES>
static void hgemm(int M, int N, int K,
                  const __half* A, int lda, const __half* B, int ldb,
                  void* C, int ldc,
                  const float* Cin = nullptr, int ldcin = 0,
                  const float* bias0 = nullptr,
                  const int* rowtok = nullptr, int rts = 1,
                  bool out_f16 = false) {
    dim3 grid(N / BN, M / BM);
    hgemm_nt_kernel<BM, BN, BK, WM, WN, STAGES>
        <<<grid, (BM / WM) * (BN / WN) * 32>>>(
            M, N, K, A, lda, B, ldb, C, ldc, Cin, ldcin, bias0, rowtok, rts,
            out_f16 ? 1 : 0);
}

// ---------------- precompute kernels ----------------
__global__ void tokens_kernel(const int* __restrict__ targets, int* __restrict__ toks) {
    int idx = blockIdx.x * blockDim.x + threadIdx.x;  // B*T
    int t = idx & (TT - 1);
    int b = idx >> 5;
    toks[idx] = (t == 0) ? EOS_IDX : targets[b * TT + t - 1];
}

// combined weights -> fp16; also pre-summed biases
__global__ void build_wcomb_kernel(const float* __restrict__ W_ih0,
                                   const float* __restrict__ W_hh0,
                                   const float* __restrict__ W_ih1,
                                   const float* __restrict__ W_hh1,
                                   const float* __restrict__ b_ih0,
                                   const float* __restrict__ b_hh0,
                                   const float* __restrict__ b_ih1,
                                   const float* __restrict__ b_hh1,
                                   __half* __restrict__ Wc0,
                                   __half* __restrict__ Wc1,
                                   float* __restrict__ bsum0,
                                   float* __restrict__ bsum1) {
    int idx = blockIdx.x * blockDim.x + threadIdx.x;
    const int N0 = G4H * (DENC + HH);
    const int N1 = G4H * (HH + HH);
    if (idx < N0) {
        int n = idx / (DENC + HH);
        int k = idx % (DENC + HH);
        float v = (k < DENC) ? W_ih0[(size_t)n * (EE + DENC) + EE + k]
                             : W_hh0[(size_t)n * HH + (k - DENC)];
        Wc0[idx] = __float2half_rn(v);
    } else if (idx < N0 + N1) {
        int r = idx - N0;
        int n = r / (HH + HH);
        int k = r % (HH + HH);
        float v = (k < HH) ? W_ih1[(size_t)n * HH + k]
                           : W_hh1[(size_t)n * HH + (k - HH)];
        Wc1[r] = __float2half_rn(v);
    } else if (idx < N0 + N1 + G4H) {
        int r = idx - N0 - N1;
        bsum0[r] = b_ih0[r] + b_hh0[r];
    } else if (idx < N0 + N1 + 2 * G4H) {
        int r = idx - N0 - N1 - G4H;
        bsum1[r] = b_ih1[r] + b_hh1[r];
    }
}

// fp16 copies of W_dec, W_enc, compact W_out[:, :PCOL]
__global__ void round_weights_kernel(const float* __restrict__ W_dec,
                                     const float* __restrict__ W_enc,
                                     const float* __restrict__ W_out,
                                     __half* __restrict__ Wdec_h,
                                     __half* __restrict__ Wenc_h,
                                     __half* __restrict__ Wout_h) {
    int idx = blockIdx.x * blockDim.x + threadIdx.x;
    const int N0 = HH * HH;
    const int N1 = HH * DENC;
    const int N2 = VV * PCOL;
    if (idx < N0) {
        Wdec_h[idx] = __float2half_rn(W_dec[idx]);
    } else if (idx < N0 + N1) {
        int r = idx - N0;
        Wenc_h[r] = __float2half_rn(W_enc[r]);
    } else if (idx < N0 + N1 + N2) {
        int r = idx - N0 - N1;
        int row = r / PCOL, col = r % PCOL;
        Wout_h[r] = __float2half_rn(W_out[(size_t)row * (HH + DENC + EE) + col]);
    }
}

// fp32 -> fp16 bulk convert (4 elems/thread)
__global__ void cvt_f16_kernel(const float* __restrict__ in,
                               __half* __restrict__ out, int n4) {
    int i = blockIdx.x * blockDim.x + threadIdx.x;
    if (i < n4) {
        float4 v = ((const float4*)in)[i];
        ((__half2*)out)[2 * i] = __floats2half2_rn(v.x, v.y);
        ((__half2*)out)[2 * i + 1] = __floats2half2_rn(v.z, v.w);
    }
}

__global__ void init_state_kernel(const float* __restrict__ h0,
                                  const float* __restrict__ c0,
                                  __half* __restrict__ xbuf,
                                  __half* __restrict__ x1buf,
                                  float* __restrict__ cb0,
                                  float* __restrict__ cb1) {
    int idx = blockIdx.x * blockDim.x + threadIdx.x;  // B*H
    int b = idx >> 9;
    int h = idx & (HH - 1);
    xbuf[(size_t)b * (DENC + HH) + DENC + h] = __float2half_rn(h0[idx]);
    x1buf[(size_t)b * (HH + HH) + HH + h] = __float2half_rn(h0[(size_t)BB * HH + idx]);
    cb0[idx] = c0[idx];
    cb1[idx] = c0[(size_t)BB * HH + idx];
}

// ---------------- attention (fused score/tanh + masked softmax + context) ----------------
__global__ void __launch_bounds__(256) attention_kernel(
    const __half* __restrict__ enc_proj,   // (B,S,H) fp16
    const __half* __restrict__ enc,        // (B,S,DENC) fp16
    const float* __restrict__ decp,        // (B,H)
    const float* __restrict__ vvec,        // (H)
    const int* __restrict__ mask,          // (B,S)
    __half* __restrict__ ctx_dst1, int ld1,
    __half* __restrict__ ctx_dst2, int ld2) {
    const int b = blockIdx.x;
    __shared__ float s_dp[HH];
    __shared__ float s_v[HH];
    __shared__ float s_w[SS];
    __shared__ float s_red[2];
    const int tid = threadIdx.x;
    const int warp = tid >> 5, lane = tid & 31;

    for (int i = tid; i < HH; i += 256) {
        s_dp[i] = decp[(size_t)b * HH + i];
        s_v[i] = vvec[i];
    }
    __syncthreads();

    for (int s = warp; s < SS; s += 8) {
        const uint2* ep = (const uint2*)(enc_proj + ((size_t)b * SS + s) * HH);
        float acc = 0.0f;
#pragma unroll
        for (int h4 = lane; h4 < HH / 4; h4 += 32) {
            uint2 raw = ep[h4];
            float2 e01 = __half22float2(*(const __half2*)&raw.x);
            float2 e23 = __half22float2(*(const __half2*)&raw.y);
            float4 sv = *(const float4*)&s_v[4 * h4];
            float4 sd = *(const float4*)&s_dp[4 * h4];
            acc += sv.x * tanh_hw(sd.x + e01.x);
            acc += sv.y * tanh_hw(sd.y + e01.y);
            acc += sv.z * tanh_hw(sd.z + e23.x);
            acc += sv.w * tanh_hw(sd.w + e23.y);
        }
#pragma unroll
        for (int o = 16; o; o >>= 1) acc += __shfl_xor_sync(0xffffffffu, acc, o);
        if (lane == 0) s_w[s] = mask[b * SS + s] ? acc : -1e30f;
    }
    __syncthreads();

    if (warp == 0) {
        float m = fmaxf(s_w[lane], s_w[lane + 32]);
#pragma unroll
        for (int o = 16; o; o >>= 1) m = fmaxf(m, __shfl_xor_sync(0xffffffffu, m, o));
        float sum = __expf(s_w[lane] - m) + __expf(s_w[lane + 32] - m);
#pragma unroll
        for (int o = 16; o; o >>= 1) sum += __shfl_xor_sync(0xffffffffu, sum, o);
        if (lane == 0) { s_red[0] = m; s_red[1] = sum; }
    }
    __syncthreads();
    const float m = s_red[0], inv = 1.0f / s_red[1];
    if (tid < SS) s_w[tid] = __expf(s_w[tid] - m) * inv;
    __syncthreads();

    // context: thread tid owns 4 d-elems; fp32 accum, fp16 store
    const __half2* eb2 = (const __half2*)(enc + (size_t)b * SS * DENC);
    float4 acc4 = make_float4(0.f, 0.f, 0.f, 0.f);
#pragma unroll 8
    for (int s = 0; s < SS; s++) {
        const float w = s_w[s];
        uint2 raw = *(const uint2*)(eb2 + (size_t)s * (DENC / 2) + 2 * tid);
        float2 e01 = __half22float2(*(const __half2*)&raw.x);
        float2 e23 = __half22float2(*(const __half2*)&raw.y);
        acc4.x += w * e01.x; acc4.y += w * e01.y;
        acc4.z += w * e23.x; acc4.w += w * e23.y;
    }
    __half2 c01 = __floats2half2_rn(acc4.x, acc4.y);
    __half2 c23 = __floats2half2_rn(acc4.z, acc4.w);
    *(__half2*)(ctx_dst1 + (size_t)b * ld1 + 4 * tid) = c01;
    *(__half2*)(ctx_dst1 + (size_t)b * ld1 + 4 * tid + 2) = c23;
    *(__half2*)(ctx_dst2 + (size_t)b * ld2 + 4 * tid) = c01;
    *(__half2*)(ctx_dst2 + (size_t)b * ld2 + 4 * tid + 2) = c23;
}

// ---------------- LSTM pointwise cell (fp16 gates in, fp16 h out) ----------------
__global__ void lstm_cell_kernel(const __half* __restrict__ gates,  // (B,4H) fp16
                                 float* __restrict__ c,             // (B,H) in/out
                                 __half* __restrict__ hA, int ldA,
                                 __half* __restrict__ hB, int ldB) {
    int idx = blockIdx.x * blockDim.x + threadIdx.x;  // B*H/4
    int b = idx / (HH / 4);
    int q = idx % (HH / 4);
    const __half* gp = gates + (size_t)b * G4H + 4 * q;
    uint2 ri = *(const uint2*)(gp);
    uint2 rf = *(const uint2*)(gp + HH);
    uint2 rg = *(const uint2*)(gp + 2 * HH);
    uint2 ro = *(const uint2*)(gp + 3 * HH);
    float2 gi01 = __half22float2(*(const __half2*)&ri.x);
    float2 gi23 = __half22float2(*(const __half2*)&ri.y);
    float2 gf01 = __half22float2(*(const __half2*)&rf.x);
    float2 gf23 = __half22float2(*(const __half2*)&rf.y);
    float2 gg01 = __half22float2(*(const __half2*)&rg.x);
    float2 gg23 = __half22float2(*(const __half2*)&rg.y);
    float2 go01 = __half22float2(*(const __half2*)&ro.x);
    float2 go23 = __half22float2(*(const __half2*)&ro.y);
    float4 cc = *(float4*)(c + (size_t)b * HH + 4 * q);
    float4 cn;
    cn.x = sigmoid_fast(gf01.x) * cc.x + sigmoid_fast(gi01.x) * tanh_fast(gg01.x);
    cn.y = sigmoid_fast(gf01.y) * cc.y + sigmoid_fast(gi01.y) * tanh_fast(gg01.y);
    cn.z = sigmoid_fast(gf23.x) * cc.z + sigmoid_fast(gi23.x) * tanh_fast(gg23.x);
    cn.w = sigmoid_fast(gf23.y) * cc.w + sigmoid_fast(gi23.y) * tanh_fast(gg23.y);
    __half2 h01 = __floats2half2_rn(sigmoid_fast(go01.x) * tanh_fast(cn.x),
                                    sigmoid_fast(go01.y) * tanh_fast(cn.y));
    __half2 h23 = __floats2half2_rn(sigmoid_fast(go23.x) * tanh_fast(cn.z),
                                    sigmoid_fast(go23.y) * tanh_fast(cn.w));
    *(float4*)(c + (size_t)b * HH + 4 * q) = cn;
    *(__half2*)(hA + (size_t)b * ldA + 4 * q) = h01;
    *(__half2*)(hA + (size_t)b * ldA + 4 * q + 2) = h23;
    *(__half2*)(hB + (size_t)b * ldB + 4 * q) = h01;
    *(__half2*)(hB + (size_t)b * ldB + 4 * q + 2) = h23;
}

// ---------------- host ----------------
extern "C" void kernel_launch(void* const* d_in, const int* in_sizes, int n_in,
                              void* d_out, int out_size) {
    const float* encoder_out = (const float*)d_in[0];
    const float* h0   = (const float*)d_in[1];
    const float* c0   = (const float*)d_in[2];
    const int*   targets = (const int*)d_in[3];
    const int*   mask    = (const int*)d_in[4];
    const float* emb   = (const float*)d_in[5];
    const float* W_enc = (const float*)d_in[6];
    const float* W_dec = (const float*)d_in[7];
    const float* vvec  = (const float*)d_in[8];
    const float* W_ih0 = (const float*)d_in[9];
    const float* W_hh0 = (const float*)d_in[10];
    const float* b_ih0 = (const float*)d_in[11];
    const float* b_hh0 = (const float*)d_in[12];
    const float* W_ih1 = (const float*)d_in[13];
    const float* W_hh1 = (const float*)d_in[14];
    const float* b_ih1 = (const float*)d_in[15];
    const float* b_hh1 = (const float*)d_in[16];
    const float* W_out = (const float*)d_in[17];
    const float* b_out = (const float*)d_in[18];
    float* out = (float*)d_out;  // (B,T,V)

    __half *p_encproj_h, *p_enc_h, *p_Wenc_h, *p_pred, *p_Wc0, *p_Wc1, *p_Wdec, *p_Wout;
    __half *p_xbuf, *p_x1buf, *p_gates;
    float *p_tokg, *p_tokp, *p_bsum0, *p_bsum1, *p_c0, *p_c1, *p_decproj;
    int* p_tokens;
    cudaGetSymbolAddress((void**)&p_encproj_h, g_encproj_h);
    cudaGetSymbolAddress((void**)&p_enc_h, g_enc_h);
    cudaGetSymbolAddress((void**)&p_Wenc_h, g_Wenc_h);
    cudaGetSymbolAddress((void**)&p_pred, g_pred);
    cudaGetSymbolAddress((void**)&p_Wc0, g_Wc0);
    cudaGetSymbolAddress((void**)&p_Wc1, g_Wc1);
    cudaGetSymbolAddress((void**)&p_Wdec, g_Wdec_h);
    cudaGetSymbolAddress((void**)&p_Wout, g_Wout_h);
    cudaGetSymbolAddress((void**)&p_tokg, g_token_gates);
    cudaGetSymbolAddress((void**)&p_tokp, g_token_preds);
    cudaGetSymbolAddress((void**)&p_bsum0, g_bsum0);
    cudaGetSymbolAddress((void**)&p_bsum1, g_bsum1);
    cudaGetSymbolAddress((void**)&p_tokens, g_tokens);
    cudaGetSymbolAddress((void**)&p_xbuf, g_xbuf);
    cudaGetSymbolAddress((void**)&p_x1buf, g_x1buf);
    cudaGetSymbolAddress((void**)&p_gates, g_gates);
    cudaGetSymbolAddress((void**)&p_c0, g_c0buf);
    cudaGetSymbolAddress((void**)&p_c1, g_c1buf);
    cudaGetSymbolAddress((void**)&p_decproj, g_decproj);

    // ---- precompute ----
    tokens_kernel<<<(BB * TT) / 256, 256>>>(targets, p_tokens);
    {
        int total = G4H * (DENC + HH) + G4H * (HH + HH) + 2 * G4H;
        build_wcomb_kernel<<<(total + 255) / 256, 256>>>(
            W_ih0, W_hh0, W_ih1, W_hh1, b_ih0, b_hh0, b_ih1, b_hh1,
            p_Wc0, p_Wc1, p_bsum0, p_bsum1);
    }
    {
        int total = HH * HH + HH * DENC + VV * PCOL;
        round_weights_kernel<<<(total + 255) / 256, 256>>>(W_dec, W_enc, W_out,
                                                           p_Wdec, p_Wenc_h, p_Wout);
    }
    {
        int n4 = (BB * SS * DENC) / 4;
        cvt_f16_kernel<<<(n4 + 255) / 256, 256>>>(encoder_out, p_enc_h, n4);
    }
    init_state_kernel<<<(BB * HH) / 256, 256>>>(h0, c0, p_xbuf, p_x1buf, p_c0, p_c1);

    // token_gates (V,4H) = emb @ W_ih0[:, :E]^T  (tf32 path, raw fp32 operands)
    {
        dim3 grid(G4H / 128, VV / 64);
        mma_nt_kernel<64, 128, 16, 32, 64, 4><<<grid, 128>>>(
            VV, G4H, EE, emb, EE, W_ih0, EE + DENC, p_tokg, G4H, nullptr);
    }
    // token_preds (V,V) = emb @ W_out[:, H+DENC:]^T + b_out
    {
        dim3 grid(VV / 64, VV / 64);
        mma_nt_kernel<64, 64, 16, 32, 32, 4><<<grid, 128>>>(
            VV, VV, EE, emb, EE, W_out + (HH + DENC), HH + DENC + EE, p_tokp, VV, b_out);
    }
    // enc_proj -> fp16 (score path)
    hgemm<128, 128, 32, 64, 32, 3>(BB * SS, HH, DENC, p_enc_h, DENC, p_Wenc_h, DENC,
                                   p_encproj_h, HH, nullptr, 0, nullptr,
                                   nullptr, 1, true);

    // ---- sequential decode ----
    for (int t = 0; t < TT; t++) {
        // dec_proj = h1 @ Wdec^T  (fp16, 128 CTAs)
        hgemm<32, 64, 32, 32, 32, 4>(BB, HH, HH, p_x1buf + HH, HH + HH, p_Wdec, HH,
                                     p_decproj, HH);

        // attention: context -> xbuf[:, :DENC] and pred[:, t, H:]
        attention_kernel<<<BB, 256>>>(p_encproj_h, p_enc_h, p_decproj, vvec, mask,
                                      p_xbuf, DENC + HH,
                                      p_pred + (size_t)t * PCOL + HH, TT * PCOL);

        // gates0 (fp16 out) = [context|h0] @ Wc0^T + token_gates[tok(b,t)] + bsum0
        hgemm<64, 64, 32, 32, 32, 4>(BB, G4H, DENC + HH, p_xbuf, DENC + HH,
                                     p_Wc0, DENC + HH, p_gates, G4H,
                                     p_tokg, G4H, p_bsum0,
                                     p_tokens + t, TT, true);
        lstm_cell_kernel<<<(BB * HH / 4) / 256, 256>>>(p_gates, p_c0,
                                                       p_x1buf, HH + HH,
                                                       p_xbuf + DENC, DENC + HH);

        // gates1 (fp16 out) = [h0n|h1] @ Wc1^T + bsum1
        hgemm<64, 64, 32, 32, 32, 4>(BB, G4H, HH + HH, p_x1buf, HH + HH,
                                     p_Wc1, HH + HH, p_gates, G4H,
                                     nullptr, 0, p_bsum1, nullptr, 1, true);
        lstm_cell_kernel<<<(BB * HH / 4) / 256, 256>>>(p_gates, p_c1,
                                                       p_x1buf + HH, HH + HH,
                                                       p_pred + (size_t)t * PCOL, TT * PCOL);
    }

    // logits: out = [h1n|context] @ Wout^T + token_preds[tok(b,t)]
    hgemm<64, 128, 32, 32, 64, 4>(BB * TT, VV, PCOL, p_pred, PCOL, p_Wout, PCOL,
                                  out, VV, p_tokp, VV, nullptr,
                                  p_tokens, 1);
}